// round 6
// baseline (speedup 1.0000x reference)
#include <cuda_runtime.h>
#include <stdint.h>
#include <math.h>

#define NBb 256
#define NSs 512
#define MASKV  -100000.0f
#define TINYF  1.17549435e-38f
#define OUT_IDX_OFF (NBb * (NSs - 1))   // 130816
#define NBLK 128

// ---------------- device scratch (no allocations) ----------------
__device__ __align__(16) float d_encout[NBb * NSs * 256];   // (b,s,h)
__device__ __align__(16) float d_refproj[NBb * NSs * 256];  // (b,s,h)
__device__ __align__(16) float d_WqT[256 * 256];            // [k][n] = Wq[n][k]
__device__ __align__(16) float d_WrefT[256 * 256];          // [k][n] = Wref[n][k]
__device__ __align__(16) float d_Wr_enc[256 * 1024];        // [k][j'] interleaved gates
__device__ __align__(16) float d_Wr_dec[256 * 1024];
__device__ __align__(16) float d_Ur_enc[2 * 1024];          // input-side collapsed (2 x 1024)
__device__ __align__(16) float d_Ur_dec[2 * 1024];
__device__ __align__(16) float d_bias_enc[1024];
__device__ __align__(16) float d_bias_dec[1024];
__device__ __align__(16) float d_hbuf[2][NBb * 256];
__device__ __align__(16) float d_cglob[NBb * 256];
__device__ __align__(16) float2 d_x2[NBb];
__device__ uint2 d_keys[NSs - 1];

// software grid barrier state
__device__ unsigned g_cnt = 0;
__device__ volatile unsigned g_gen = 0;

__device__ __forceinline__ void gridbar() {
    __syncthreads();
    if (threadIdx.x == 0) {
        unsigned gen = g_gen;
        __threadfence();
        if (atomicAdd(&g_cnt, 1u) == NBLK - 1) {
            g_cnt = 0;
            __threadfence();
            g_gen = gen + 1;
        } else {
            while (g_gen == gen) __nanosleep(32);
            __threadfence();
        }
    }
    __syncthreads();
}

// ---------------- threefry2x32 (exact JAX) ----------------
__device__ __forceinline__ void threefry2x32(uint32_t k0, uint32_t k1,
                                             uint32_t c0, uint32_t c1,
                                             uint32_t& o0, uint32_t& o1) {
    uint32_t ks2 = k0 ^ k1 ^ 0x1BD11BDAu;
    uint32_t x0 = c0 + k0, x1 = c1 + k1;
#define RND(r) { x0 += x1; x1 = (x1 << (r)) | (x1 >> (32 - (r))); x1 ^= x0; }
    RND(13) RND(15) RND(26) RND(6)
    x0 += k1;  x1 += ks2 + 1u;
    RND(17) RND(29) RND(16) RND(24)
    x0 += ks2; x1 += k0 + 2u;
    RND(13) RND(15) RND(26) RND(6)
    x0 += k0;  x1 += k1 + 3u;
    RND(17) RND(29) RND(16) RND(24)
    x0 += k1;  x1 += ks2 + 4u;
    RND(13) RND(15) RND(26) RND(6)
    x0 += ks2; x1 += k0 + 5u;
#undef RND
    o0 = x0; o1 = x1;
}

__device__ __forceinline__ float sigm(float x) {
    return 0.5f + 0.5f * tanhf(0.5f * x);
}

// map interleaved col j' -> original gate row j
__device__ __forceinline__ int jmap(int jp) {
    int ht = jp >> 6, rem = jp & 63, hh = rem >> 2, g = rem & 3;
    return g * 256 + ht * 16 + hh;
}

// ---------------- init (weight reshapes, keys, feedback init) ----------------
__global__ void k_init(const float* __restrict__ inp, const float* __restrict__ We,
                       const float* __restrict__ eWih, const float* __restrict__ eWhh,
                       const float* __restrict__ ebih, const float* __restrict__ ebhh,
                       const float* __restrict__ dWih, const float* __restrict__ dWhh,
                       const float* __restrict__ dbih, const float* __restrict__ dbhh,
                       const float* __restrict__ Wq,  const float* __restrict__ Wref,
                       float* __restrict__ out) {
    int idx = blockIdx.x * 256 + threadIdx.x;   // 262144 threads
    if (idx < 262144) {
        int k = idx >> 10, jp = idx & 1023;
        int j = jmap(jp);
        d_Wr_enc[idx] = eWhh[j * 256 + k];
        d_Wr_dec[idx] = dWhh[j * 256 + k];
    }
    if (idx < 65536) {
        int k = idx >> 8, n = idx & 255;
        d_WqT[idx]   = Wq[n * 256 + k];
        d_WrefT[idx] = Wref[n * 256 + k];
    }
    if (idx < 2048) {
        int i = idx >> 10, jp = idx & 1023;
        int j = jmap(jp);
        float se = 0.0f, sd = 0.0f;
        for (int e = 0; e < 256; ++e) {
            float w = We[i * 256 + e];
            se += w * eWih[j * 256 + e];
            sd += w * dWih[j * 256 + e];
        }
        d_Ur_enc[idx] = se;
        d_Ur_dec[idx] = sd;
    }
    if (idx < 1024) {
        int j = jmap(idx);
        d_bias_enc[idx] = ebih[j] + ebhh[j];
        d_bias_dec[idx] = dbih[j] + dbhh[j];
    }
    if (idx < NSs - 1) {
        uint32_t o0, o1;
        threefry2x32(0u, 1u, 0u, (uint32_t)idx, o0, o1);
        d_keys[idx] = make_uint2(o0, o1);
    }
    if (idx < NBb) {
        d_x2[idx] = make_float2(inp[idx * 1024], inp[idx * 1024 + 1]);  // emb feed = inputs[b,0,:]
        out[OUT_IDX_OFF + idx * NSs] = 0.0f;                            // indices[:,0] = START
    }
}

// ---------------- shared GEMM helper macro-ish (inlined in both kernels) ----------------

// ---------------- persistent encoder ----------------
__global__ void __launch_bounds__(256, 1) k_enc(const float* __restrict__ inp) {
    __shared__ __align__(16) float As[32][33];
    __shared__ __align__(16) float Bs[32][68];
    int tid = threadIdx.x;
    int tx = tid & 15, ty = tid >> 4;
    int bt = blockIdx.x >> 4, ht = blockIdx.x & 15;
    int b0 = bt * 32;
    int jc = ht * 64;
    int H = ht * 16 + tx;
    int b_r0 = b0 + ty, b_r1 = b0 + 16 + ty;

    float u0[4], u1[4], bb[4];
#pragma unroll
    for (int g = 0; g < 4; ++g) {
        int jp = jc + tx * 4 + g;
        u0[g] = d_Ur_enc[jp];
        u1[g] = d_Ur_enc[1024 + jp];
        bb[g] = d_bias_enc[jp];
    }
    float c0 = 0.0f, c1 = 0.0f;

    int a_br = tid >> 3, a_k4 = (tid & 7) * 4;
    int b_kk = tid >> 3, b_j8 = (tid & 7) * 8;

    for (int t = 0; t < 512; ++t) {
        float acc0[4] = {0, 0, 0, 0}, acc1[4] = {0, 0, 0, 0};
        if (t > 0) {
            const float* hb = d_hbuf[(t & 1) ^ 1];
            for (int kt = 0; kt < 256; kt += 32) {
                float4 a = __ldcg((const float4*)&hb[(b0 + a_br) * 256 + kt + a_k4]);
                As[a_k4 + 0][a_br] = a.x; As[a_k4 + 1][a_br] = a.y;
                As[a_k4 + 2][a_br] = a.z; As[a_k4 + 3][a_br] = a.w;
                const float* wp = &d_Wr_enc[(kt + b_kk) * 1024 + jc + b_j8];
                *(float4*)&Bs[b_kk][b_j8]     = *(const float4*)wp;
                *(float4*)&Bs[b_kk][b_j8 + 4] = *(const float4*)(wp + 4);
                __syncthreads();
#pragma unroll
                for (int kk = 0; kk < 32; ++kk) {
                    float av0 = As[kk][ty];
                    float av1 = As[kk][16 + ty];
                    float4 w = *(const float4*)&Bs[kk][tx * 4];
                    acc0[0] += av0 * w.x; acc0[1] += av0 * w.y; acc0[2] += av0 * w.z; acc0[3] += av0 * w.w;
                    acc1[0] += av1 * w.x; acc1[1] += av1 * w.y; acc1[2] += av1 * w.z; acc1[3] += av1 * w.w;
                }
                __syncthreads();
            }
        }
        float x00 = inp[b_r0 * 1024 + t * 2], x01 = inp[b_r0 * 1024 + t * 2 + 1];
        float x10 = inp[b_r1 * 1024 + t * 2], x11 = inp[b_r1 * 1024 + t * 2 + 1];
        float g0[4], g1[4];
#pragma unroll
        for (int g = 0; g < 4; ++g) {
            g0[g] = acc0[g] + bb[g] + x00 * u0[g] + x01 * u1[g];
            g1[g] = acc1[g] + bb[g] + x10 * u0[g] + x11 * u1[g];
        }
        c0 = sigm(g0[1]) * c0 + sigm(g0[0]) * tanhf(g0[2]);
        float h0v = sigm(g0[3]) * tanhf(c0);
        c1 = sigm(g1[1]) * c1 + sigm(g1[0]) * tanhf(g1[2]);
        float h1v = sigm(g1[3]) * tanhf(c1);
        float* hw = d_hbuf[t & 1];
        __stcg(&hw[b_r0 * 256 + H], h0v);
        __stcg(&hw[b_r1 * 256 + H], h1v);
        __stcg(&d_encout[(b_r0 * 512 + t) * 256 + H], h0v);
        __stcg(&d_encout[(b_r1 * 512 + t) * 256 + H], h1v);
        gridbar();
    }
    __stcg(&d_cglob[b_r0 * 256 + H], c0);
    __stcg(&d_cglob[b_r1 * 256 + H], c1);
}

// ---------------- ref_proj = enc_out @ Wref^T  (131072 x 256 x 256) ----------------
__global__ void k_refproj() {
    __shared__ __align__(16) float As[16][68];
    __shared__ __align__(16) float Bs[16][68];
    int tid = threadIdx.x;
    int tx = tid & 15, ty = tid >> 4;
    int n0 = blockIdx.x * 64;
    int m0 = blockIdx.y * 64;
    float acc[4][4];
#pragma unroll
    for (int i = 0; i < 4; i++)
#pragma unroll
        for (int j = 0; j < 4; j++) acc[i][j] = 0.0f;

    int lm  = tid >> 2;
    int lk4 = (tid & 3) * 4;

    for (int kt = 0; kt < 16; ++kt) {
        int kb = kt * 16;
        float4 av = *reinterpret_cast<const float4*>(&d_encout[(m0 + lm) * 256 + kb + lk4]);
        As[lk4 + 0][lm] = av.x; As[lk4 + 1][lm] = av.y;
        As[lk4 + 2][lm] = av.z; As[lk4 + 3][lm] = av.w;
#pragma unroll
        for (int i = 0; i < 4; ++i) {
            int li = tid + i * 256;
            int kk = li >> 6, nn = li & 63;
            Bs[kk][nn] = d_WrefT[(kb + kk) * 256 + n0 + nn];
        }
        __syncthreads();
#pragma unroll
        for (int kk = 0; kk < 16; ++kk) {
            float4 a = *reinterpret_cast<const float4*>(&As[kk][ty * 4]);
            float4 w = *reinterpret_cast<const float4*>(&Bs[kk][tx * 4]);
            acc[0][0] += a.x * w.x; acc[0][1] += a.x * w.y; acc[0][2] += a.x * w.z; acc[0][3] += a.x * w.w;
            acc[1][0] += a.y * w.x; acc[1][1] += a.y * w.y; acc[1][2] += a.y * w.z; acc[1][3] += a.y * w.w;
            acc[2][0] += a.z * w.x; acc[2][1] += a.z * w.y; acc[2][2] += a.z * w.z; acc[2][3] += a.z * w.w;
            acc[3][0] += a.w * w.x; acc[3][1] += a.w * w.y; acc[3][2] += a.w * w.z; acc[3][3] += a.w * w.w;
        }
        __syncthreads();
    }
#pragma unroll
    for (int r = 0; r < 4; ++r) {
        float4 o = make_float4(acc[r][0], acc[r][1], acc[r][2], acc[r][3]);
        *reinterpret_cast<float4*>(&d_refproj[(m0 + ty * 4 + r) * 256 + n0 + tx * 4]) = o;
    }
}

// ---------------- persistent decoder ----------------
__global__ void __launch_bounds__(256, 1) k_dec(const float* __restrict__ inp,
                                                const float* __restrict__ vvec,
                                                float* __restrict__ out) {
    __shared__ __align__(16) float As[32][33];
    __shared__ __align__(16) float Bs[32][68];
    __shared__ float sh_h[2][256];
    __shared__ float sh_q[2][256];
    __shared__ float sh_v[256];
    __shared__ float sh_logit[2][512];
    __shared__ unsigned sh_mask[2][16];
    __shared__ float sh_bz[8];
    __shared__ int   sh_bi[8];
    __shared__ int   sh_ch[2];

    int tid = threadIdx.x;
    int tx = tid & 15, ty = tid >> 4;
    int bt = blockIdx.x >> 4, ht = blockIdx.x & 15;
    int b0 = bt * 32;
    int jc = ht * 64;
    int H = ht * 16 + tx;
    int b_r0 = b0 + ty, b_r1 = b0 + 16 + ty;
    int ab = blockIdx.x * 2;           // attn rows ab, ab+1
    int w = tid >> 5, lane = tid & 31;

    float u0[4], u1[4], bb[4];
#pragma unroll
    for (int g = 0; g < 4; ++g) {
        int jp = jc + tx * 4 + g;
        u0[g] = d_Ur_dec[jp];
        u1[g] = d_Ur_dec[1024 + jp];
        bb[g] = d_bias_dec[jp];
    }
    float c0 = __ldcg(&d_cglob[b_r0 * 256 + H]);
    float c1 = __ldcg(&d_cglob[b_r1 * 256 + H]);
    sh_v[tid] = vvec[tid];
    if (tid < 32) sh_mask[tid >> 4][tid & 15] = 0u;
    __syncthreads();
    if (tid < 2) sh_mask[tid][0] = 1u;   // START=0 masked
    __syncthreads();

    int a_br = tid >> 3, a_k4 = (tid & 7) * 4;
    int b_kk = tid >> 3, b_j8 = (tid & 7) * 8;

    for (int td = 0; td < 511; ++td) {
        // ---- phase A: LSTM gates ----
        float acc0[4] = {0, 0, 0, 0}, acc1[4] = {0, 0, 0, 0};
        const float* hb = d_hbuf[(td & 1) ^ 1];
        for (int kt = 0; kt < 256; kt += 32) {
            float4 a = __ldcg((const float4*)&hb[(b0 + a_br) * 256 + kt + a_k4]);
            As[a_k4 + 0][a_br] = a.x; As[a_k4 + 1][a_br] = a.y;
            As[a_k4 + 2][a_br] = a.z; As[a_k4 + 3][a_br] = a.w;
            const float* wp = &d_Wr_dec[(kt + b_kk) * 1024 + jc + b_j8];
            *(float4*)&Bs[b_kk][b_j8]     = *(const float4*)wp;
            *(float4*)&Bs[b_kk][b_j8 + 4] = *(const float4*)(wp + 4);
            __syncthreads();
#pragma unroll
            for (int kk = 0; kk < 32; ++kk) {
                float av0 = As[kk][ty];
                float av1 = As[kk][16 + ty];
                float4 ww = *(const float4*)&Bs[kk][tx * 4];
                acc0[0] += av0 * ww.x; acc0[1] += av0 * ww.y; acc0[2] += av0 * ww.z; acc0[3] += av0 * ww.w;
                acc1[0] += av1 * ww.x; acc1[1] += av1 * ww.y; acc1[2] += av1 * ww.z; acc1[3] += av1 * ww.w;
            }
            __syncthreads();
        }
        float2 xv0 = __ldcg(&d_x2[b_r0]);
        float2 xv1 = __ldcg(&d_x2[b_r1]);
        float g0[4], g1[4];
#pragma unroll
        for (int g = 0; g < 4; ++g) {
            g0[g] = acc0[g] + bb[g] + xv0.x * u0[g] + xv0.y * u1[g];
            g1[g] = acc1[g] + bb[g] + xv1.x * u0[g] + xv1.y * u1[g];
        }
        c0 = sigm(g0[1]) * c0 + sigm(g0[0]) * tanhf(g0[2]);
        float h0v = sigm(g0[3]) * tanhf(c0);
        c1 = sigm(g1[1]) * c1 + sigm(g1[0]) * tanhf(g1[2]);
        float h1v = sigm(g1[3]) * tanhf(c1);
        float* hw = d_hbuf[td & 1];
        __stcg(&hw[b_r0 * 256 + H], h0v);
        __stcg(&hw[b_r1 * 256 + H], h1v);
        gridbar();

        // ---- phase B: q, attention, sampling (block owns rows ab, ab+1) ----
        const float* hn = d_hbuf[td & 1];
        {
            int r = tid >> 7;                       // 0,1 over two halves? need 512 loads
            // 512 floats over 256 threads: 2 each
            int i0 = tid, i1 = tid + 256;
            sh_h[i0 >> 8][i0 & 255] = __ldcg(&hn[(ab + (i0 >> 8)) * 256 + (i0 & 255)]);
            sh_h[i1 >> 8][i1 & 255] = __ldcg(&hn[(ab + (i1 >> 8)) * 256 + (i1 & 255)]);
            (void)r;
        }
        __syncthreads();
        {
            float q0 = 0.0f, q1 = 0.0f;
#pragma unroll 4
            for (int k = 0; k < 256; ++k) {
                float wq = d_WqT[k * 256 + tid];
                q0 += sh_h[0][k] * wq;
                q1 += sh_h[1][k] * wq;
            }
            sh_q[0][tid] = q0;
            sh_q[1][tid] = q1;
        }
        __syncthreads();

        uint2 key = d_keys[td];
        int r = w & 1;          // row within pair
        int ws = w >> 1;        // 0..3
        float bz = -1e30f; int bi = 0x7fffffff;
        for (int s = ws; s < 512; s += 4) {
            bool masked = (sh_mask[r][s >> 5] >> (s & 31)) & 1u;
            float lg;
            if (masked) {
                lg = MASKV;
            } else {
                const float* rp = &d_refproj[((ab + r) * 512 + s) * 256];
                float p = 0.0f;
#pragma unroll
                for (int k = lane; k < 256; k += 32)
                    p += sh_v[k] * tanhf(sh_q[r][k] + rp[k]);
                p += __shfl_xor_sync(0xffffffffu, p, 16);
                p += __shfl_xor_sync(0xffffffffu, p, 8);
                p += __shfl_xor_sync(0xffffffffu, p, 4);
                p += __shfl_xor_sync(0xffffffffu, p, 2);
                p += __shfl_xor_sync(0xffffffffu, p, 1);
                lg = p;
            }
            if (lane == 0) {
                sh_logit[r][s] = lg;
                if (!masked) {
                    uint32_t o0, o1;
                    threefry2x32(key.x, key.y, 0u, (uint32_t)((ab + r) * 512 + s), o0, o1);
                    uint32_t bits = o0 ^ o1;
                    float f = __uint_as_float((bits >> 9) | 0x3f800000u) - 1.0f;
                    float u = fmaxf(TINYF, f + TINYF);
                    float gmb = -logf(-logf(u));
                    float z = lg + gmb;
                    if (z > bz) { bz = z; bi = s; }
                }
            }
        }
        if (lane == 0) { sh_bz[w] = bz; sh_bi[w] = bi; }
        __syncthreads();

        if (w < 2) {
            int rr = w;
            if (lane == 0) {
                float bv = -1e30f; int bidx = 0x7fffffff;
#pragma unroll
                for (int i = rr; i < 8; i += 2) {
                    if (sh_bz[i] > bv || (sh_bz[i] == bv && sh_bi[i] < bidx)) {
                        bv = sh_bz[i]; bidx = sh_bi[i];
                    }
                }
                sh_ch[rr] = bidx;
            }
            __syncwarp();
            int chosen = sh_ch[rr];
            float m = -1e30f;
            for (int s = lane; s < 512; s += 32) m = fmaxf(m, sh_logit[rr][s]);
            m = fmaxf(m, __shfl_xor_sync(0xffffffffu, m, 16));
            m = fmaxf(m, __shfl_xor_sync(0xffffffffu, m, 8));
            m = fmaxf(m, __shfl_xor_sync(0xffffffffu, m, 4));
            m = fmaxf(m, __shfl_xor_sync(0xffffffffu, m, 2));
            m = fmaxf(m, __shfl_xor_sync(0xffffffffu, m, 1));
            float es = 0.0f;
            for (int s = lane; s < 512; s += 32) es += expf(sh_logit[rr][s] - m);
            es += __shfl_xor_sync(0xffffffffu, es, 16);
            es += __shfl_xor_sync(0xffffffffu, es, 8);
            es += __shfl_xor_sync(0xffffffffu, es, 4);
            es += __shfl_xor_sync(0xffffffffu, es, 2);
            es += __shfl_xor_sync(0xffffffffu, es, 1);
            if (lane == 0) {
                int b = ab + rr;
                float lp = sh_logit[rr][chosen] - m - logf(es);
                out[b * (NSs - 1) + td] = lp;
                out[OUT_IDX_OFF + b * NSs + td + 1] = (float)chosen;
                sh_mask[rr][chosen >> 5] |= (1u << (chosen & 31));
                float2 nx;
                nx.x = inp[b * 1024 + chosen * 2];
                nx.y = inp[b * 1024 + chosen * 2 + 1];
                __stcg(&d_x2[b], nx);
            }
        }
        gridbar();
    }
}

// ---------------- host ----------------
extern "C" void kernel_launch(void* const* d_in, const int* in_sizes, int n_in,
                              void* d_out, int out_size) {
    const float* inputs  = (const float*)d_in[0];
    const float* W_embed = (const float*)d_in[1];
    const float* eWih    = (const float*)d_in[2];
    const float* eWhh    = (const float*)d_in[3];
    const float* ebih    = (const float*)d_in[4];
    const float* ebhh    = (const float*)d_in[5];
    const float* dWih    = (const float*)d_in[6];
    const float* dWhh    = (const float*)d_in[7];
    const float* dbih    = (const float*)d_in[8];
    const float* dbhh    = (const float*)d_in[9];
    const float* Wq      = (const float*)d_in[10];
    const float* Wref    = (const float*)d_in[11];
    const float* v       = (const float*)d_in[12];
    float* out = (float*)d_out;

    k_init<<<1024, 256>>>(inputs, W_embed, eWih, eWhh, ebih, ebhh,
                          dWih, dWhh, dbih, dbhh, Wq, Wref, out);
    k_enc<<<NBLK, 256>>>(inputs);
    k_refproj<<<dim3(4, 2048), 256>>>();
    k_dec<<<NBLK, 256>>>(inputs, v, out);
}

// round 7
// speedup vs baseline: 1.2442x; 1.2442x over previous
#include <cuda_runtime.h>
#include <stdint.h>
#include <math.h>

#define NBb 256
#define NSs 512
#define MASKV  -100000.0f
#define TINYF  1.17549435e-38f
#define OUT_IDX_OFF (NBb * (NSs - 1))   // 130816
#define NBLK 128

// ---------------- device scratch (no allocations) ----------------
__device__ __align__(16) float d_encout[NBb * NSs * 256];   // (b,s,h)
__device__ __align__(16) float d_refproj[NBb * NSs * 256];  // (b,s,h)
__device__ __align__(16) float d_gumb[(NSs - 1) * NBb * NSs]; // (t,b,s) gumbel table
__device__ __align__(16) float d_WqT[256 * 256];            // [k][n] = Wq[n][k]
__device__ __align__(16) float d_WrefT[256 * 256];          // [k][n] = Wref[n][k]
__device__ __align__(16) float d_Wr_enc[256 * 1024];        // [k][j'] interleaved gates
__device__ __align__(16) float d_Wr_dec[256 * 1024];
__device__ __align__(16) float d_Ur_enc[2 * 1024];          // input-side collapsed (2 x 1024)
__device__ __align__(16) float d_Ur_dec[2 * 1024];
__device__ __align__(16) float d_bias_enc[1024];
__device__ __align__(16) float d_bias_dec[1024];
__device__ __align__(16) float d_hbuf[2][NBb * 256];
__device__ __align__(16) float d_cglob[NBb * 256];
__device__ __align__(16) float2 d_x2[NBb];
__device__ uint2 d_keys[NSs - 1];

// software grid barrier state
__device__ unsigned g_cnt = 0;
__device__ volatile unsigned g_gen = 0;

__device__ __forceinline__ void gridbar() {
    __syncthreads();
    if (threadIdx.x == 0) {
        unsigned gen = g_gen;
        __threadfence();
        if (atomicAdd(&g_cnt, 1u) == NBLK - 1) {
            g_cnt = 0;
            __threadfence();
            g_gen = gen + 1;
        } else {
            while (g_gen == gen) __nanosleep(32);
            __threadfence();
        }
    }
    __syncthreads();
}

// ---------------- threefry2x32 (exact JAX) ----------------
__device__ __forceinline__ void threefry2x32(uint32_t k0, uint32_t k1,
                                             uint32_t c0, uint32_t c1,
                                             uint32_t& o0, uint32_t& o1) {
    uint32_t ks2 = k0 ^ k1 ^ 0x1BD11BDAu;
    uint32_t x0 = c0 + k0, x1 = c1 + k1;
#define RND(r) { x0 += x1; x1 = (x1 << (r)) | (x1 >> (32 - (r))); x1 ^= x0; }
    RND(13) RND(15) RND(26) RND(6)
    x0 += k1;  x1 += ks2 + 1u;
    RND(17) RND(29) RND(16) RND(24)
    x0 += ks2; x1 += k0 + 2u;
    RND(13) RND(15) RND(26) RND(6)
    x0 += k0;  x1 += k1 + 3u;
    RND(17) RND(29) RND(16) RND(24)
    x0 += k1;  x1 += ks2 + 4u;
    RND(13) RND(15) RND(26) RND(6)
    x0 += ks2; x1 += k0 + 5u;
#undef RND
    o0 = x0; o1 = x1;
}

__device__ __forceinline__ float sigm(float x) {
    return 0.5f + 0.5f * tanhf(0.5f * x);
}

// map interleaved col j' -> original gate row j
__device__ __forceinline__ int jmap(int jp) {
    int ht = jp >> 6, rem = jp & 63, hh = rem >> 2, g = rem & 3;
    return g * 256 + ht * 16 + hh;
}

// ---------------- init (weight reshapes, keys, feedback init) ----------------
__global__ void k_init(const float* __restrict__ inp, const float* __restrict__ We,
                       const float* __restrict__ eWih, const float* __restrict__ eWhh,
                       const float* __restrict__ ebih, const float* __restrict__ ebhh,
                       const float* __restrict__ dWih, const float* __restrict__ dWhh,
                       const float* __restrict__ dbih, const float* __restrict__ dbhh,
                       const float* __restrict__ Wq,  const float* __restrict__ Wref,
                       float* __restrict__ out) {
    int idx = blockIdx.x * 256 + threadIdx.x;   // 262144 threads
    if (idx < 262144) {
        int k = idx >> 10, jp = idx & 1023;
        int j = jmap(jp);
        d_Wr_enc[idx] = eWhh[j * 256 + k];
        d_Wr_dec[idx] = dWhh[j * 256 + k];
    }
    if (idx < 65536) {
        int k = idx >> 8, n = idx & 255;
        d_WqT[idx]   = Wq[n * 256 + k];
        d_WrefT[idx] = Wref[n * 256 + k];
    }
    if (idx < 2048) {
        int i = idx >> 10, jp = idx & 1023;
        int j = jmap(jp);
        float se = 0.0f, sd = 0.0f;
        for (int e = 0; e < 256; ++e) {
            float w = We[i * 256 + e];
            se += w * eWih[j * 256 + e];
            sd += w * dWih[j * 256 + e];
        }
        d_Ur_enc[idx] = se;
        d_Ur_dec[idx] = sd;
    }
    if (idx < 1024) {
        int j = jmap(idx);
        d_bias_enc[idx] = ebih[j] + ebhh[j];
        d_bias_dec[idx] = dbih[j] + dbhh[j];
    }
    if (idx < NSs - 1) {
        uint32_t o0, o1;
        threefry2x32(0u, 1u, 0u, (uint32_t)idx, o0, o1);
        d_keys[idx] = make_uint2(o0, o1);
    }
    if (idx < NBb) {
        d_x2[idx] = make_float2(inp[idx * 1024], inp[idx * 1024 + 1]);  // emb feed = inputs[b,0,:]
        out[OUT_IDX_OFF + idx * NSs] = 0.0f;                            // indices[:,0] = START
    }
}

// ---------------- precompute all gumbel noise (pure function of keys) ----------------
__global__ void k_gumb() {
    int blk = blockIdx.x;            // 0 .. 511*256-1
    int t = blk >> 8;                // step
    int b = blk & 255;               // batch row
    int s = threadIdx.x;             // 0..511
    uint2 key = d_keys[t];
    uint32_t o0, o1;
    threefry2x32(key.x, key.y, 0u, (uint32_t)(b * 512 + s), o0, o1);
    uint32_t bits = o0 ^ o1;
    float f = __uint_as_float((bits >> 9) | 0x3f800000u) - 1.0f;
    float u = fmaxf(TINYF, f + TINYF);
    d_gumb[blk * 512 + s] = -logf(-logf(u));
}

// ---------------- persistent encoder (512 threads: 1 (b,h) cell per thread) ----------------
__global__ void __launch_bounds__(512, 1) k_enc(const float* __restrict__ inp) {
    __shared__ __align__(16) float As[32][33];
    __shared__ __align__(16) float Bs[32][68];
    int tid = threadIdx.x;
    int tx = tid & 15, ty = tid >> 4;            // ty 0..31 = batch row in tile
    int bt = blockIdx.x >> 4, ht = blockIdx.x & 15;
    int b0 = bt * 32;
    int jc = ht * 64;
    int H = ht * 16 + tx;
    int brow = b0 + ty;

    float u0[4], u1[4], bb[4];
#pragma unroll
    for (int g = 0; g < 4; ++g) {
        int jp = jc + tx * 4 + g;
        u0[g] = d_Ur_enc[jp];
        u1[g] = d_Ur_enc[1024 + jp];
        bb[g] = d_bias_enc[jp];
    }
    float c0 = 0.0f;

    int a_br = tid >> 4, a_k2 = (tid & 15) * 2;
    int b_kk = tid >> 4, b_j4 = (tid & 15) * 4;

    for (int t = 0; t < 512; ++t) {
        float acc0[4] = {0, 0, 0, 0};
        if (t > 0) {
            const float* hb = d_hbuf[(t & 1) ^ 1];
            for (int kt = 0; kt < 256; kt += 32) {
                float2 a = __ldcg((const float2*)&hb[(b0 + a_br) * 256 + kt + a_k2]);
                As[a_k2 + 0][a_br] = a.x; As[a_k2 + 1][a_br] = a.y;
                *(float4*)&Bs[b_kk][b_j4] =
                    *(const float4*)&d_Wr_enc[(kt + b_kk) * 1024 + jc + b_j4];
                __syncthreads();
#pragma unroll
                for (int kk = 0; kk < 32; ++kk) {
                    float av0 = As[kk][ty];
                    float4 w = *(const float4*)&Bs[kk][tx * 4];
                    acc0[0] += av0 * w.x; acc0[1] += av0 * w.y;
                    acc0[2] += av0 * w.z; acc0[3] += av0 * w.w;
                }
                __syncthreads();
            }
        }
        float x00 = inp[brow * 1024 + t * 2], x01 = inp[brow * 1024 + t * 2 + 1];
        float g0[4];
#pragma unroll
        for (int g = 0; g < 4; ++g) {
            g0[g] = acc0[g] + bb[g] + x00 * u0[g] + x01 * u1[g];
        }
        c0 = sigm(g0[1]) * c0 + sigm(g0[0]) * tanhf(g0[2]);
        float h0v = sigm(g0[3]) * tanhf(c0);
        float* hw = d_hbuf[t & 1];
        __stcg(&hw[brow * 256 + H], h0v);
        __stcg(&d_encout[(brow * 512 + t) * 256 + H], h0v);
        gridbar();
    }
    __stcg(&d_cglob[brow * 256 + H], c0);
}

// ---------------- ref_proj = enc_out @ Wref^T  (131072 x 256 x 256) ----------------
__global__ void k_refproj() {
    __shared__ __align__(16) float As[16][68];
    __shared__ __align__(16) float Bs[16][68];
    int tid = threadIdx.x;
    int tx = tid & 15, ty = tid >> 4;
    int n0 = blockIdx.x * 64;
    int m0 = blockIdx.y * 64;
    float acc[4][4];
#pragma unroll
    for (int i = 0; i < 4; i++)
#pragma unroll
        for (int j = 0; j < 4; j++) acc[i][j] = 0.0f;

    int lm  = tid >> 2;
    int lk4 = (tid & 3) * 4;

    for (int kt = 0; kt < 16; ++kt) {
        int kb = kt * 16;
        float4 av = *reinterpret_cast<const float4*>(&d_encout[(m0 + lm) * 256 + kb + lk4]);
        As[lk4 + 0][lm] = av.x; As[lk4 + 1][lm] = av.y;
        As[lk4 + 2][lm] = av.z; As[lk4 + 3][lm] = av.w;
#pragma unroll
        for (int i = 0; i < 4; ++i) {
            int li = tid + i * 256;
            int kk = li >> 6, nn = li & 63;
            Bs[kk][nn] = d_WrefT[(kb + kk) * 256 + n0 + nn];
        }
        __syncthreads();
#pragma unroll
        for (int kk = 0; kk < 16; ++kk) {
            float4 a = *reinterpret_cast<const float4*>(&As[kk][ty * 4]);
            float4 w = *reinterpret_cast<const float4*>(&Bs[kk][tx * 4]);
            acc[0][0] += a.x * w.x; acc[0][1] += a.x * w.y; acc[0][2] += a.x * w.z; acc[0][3] += a.x * w.w;
            acc[1][0] += a.y * w.x; acc[1][1] += a.y * w.y; acc[1][2] += a.y * w.z; acc[1][3] += a.y * w.w;
            acc[2][0] += a.z * w.x; acc[2][1] += a.z * w.y; acc[2][2] += a.z * w.z; acc[2][3] += a.z * w.w;
            acc[3][0] += a.w * w.x; acc[3][1] += a.w * w.y; acc[3][2] += a.w * w.z; acc[3][3] += a.w * w.w;
        }
        __syncthreads();
    }
#pragma unroll
    for (int r = 0; r < 4; ++r) {
        float4 o = make_float4(acc[r][0], acc[r][1], acc[r][2], acc[r][3]);
        *reinterpret_cast<float4*>(&d_refproj[(m0 + ty * 4 + r) * 256 + n0 + tx * 4]) = o;
    }
}

// ---------------- persistent decoder (512 threads / block) ----------------
__global__ void __launch_bounds__(512, 1) k_dec(const float* __restrict__ inp,
                                                const float* __restrict__ vvec,
                                                float* __restrict__ out) {
    __shared__ __align__(16) float As[32][33];
    __shared__ __align__(16) float Bs[32][68];
    __shared__ float sh_h[2][256];
    __shared__ float sh_q[2][256];
    __shared__ float sh_v[256];
    __shared__ float sh_logit[2][512];
    __shared__ unsigned sh_mask[2][16];
    __shared__ float sh_bz[16];
    __shared__ int   sh_bi[16];
    __shared__ int   sh_ch[2];

    int tid = threadIdx.x;
    int tx = tid & 15, ty = tid >> 4;          // ty 0..31
    int bt = blockIdx.x >> 4, ht = blockIdx.x & 15;
    int b0 = bt * 32;
    int jc = ht * 64;
    int H = ht * 16 + tx;
    int brow = b0 + ty;
    int ab = blockIdx.x * 2;                   // attention rows ab, ab+1
    int w = tid >> 5, lane = tid & 31;

    float u0[4], u1[4], bb[4];
#pragma unroll
    for (int g = 0; g < 4; ++g) {
        int jp = jc + tx * 4 + g;
        u0[g] = d_Ur_dec[jp];
        u1[g] = d_Ur_dec[1024 + jp];
        bb[g] = d_bias_dec[jp];
    }
    float c0 = __ldcg(&d_cglob[brow * 256 + H]);
    if (tid < 256) sh_v[tid] = vvec[tid];
    if (tid < 32) sh_mask[tid >> 4][tid & 15] = 0u;
    __syncthreads();
    if (tid < 2) sh_mask[tid][0] = 1u;   // START=0 masked
    __syncthreads();

    int a_br = tid >> 4, a_k2 = (tid & 15) * 2;
    int b_kk = tid >> 4, b_j4 = (tid & 15) * 4;

    for (int td = 0; td < 511; ++td) {
        // ---- phase A: LSTM gates ----
        float acc0[4] = {0, 0, 0, 0};
        const float* hb = d_hbuf[(td & 1) ^ 1];
        for (int kt = 0; kt < 256; kt += 32) {
            float2 a = __ldcg((const float2*)&hb[(b0 + a_br) * 256 + kt + a_k2]);
            As[a_k2 + 0][a_br] = a.x; As[a_k2 + 1][a_br] = a.y;
            *(float4*)&Bs[b_kk][b_j4] =
                *(const float4*)&d_Wr_dec[(kt + b_kk) * 1024 + jc + b_j4];
            __syncthreads();
#pragma unroll
            for (int kk = 0; kk < 32; ++kk) {
                float av0 = As[kk][ty];
                float4 ww = *(const float4*)&Bs[kk][tx * 4];
                acc0[0] += av0 * ww.x; acc0[1] += av0 * ww.y;
                acc0[2] += av0 * ww.z; acc0[3] += av0 * ww.w;
            }
            __syncthreads();
        }
        float2 xv0 = __ldcg(&d_x2[brow]);
        float g0[4];
#pragma unroll
        for (int g = 0; g < 4; ++g) {
            g0[g] = acc0[g] + bb[g] + xv0.x * u0[g] + xv0.y * u1[g];
        }
        c0 = sigm(g0[1]) * c0 + sigm(g0[0]) * tanhf(g0[2]);
        float h0v = sigm(g0[3]) * tanhf(c0);
        float* hw = d_hbuf[td & 1];
        __stcg(&hw[brow * 256 + H], h0v);
        gridbar();

        // ---- phase B: q, attention, sampling (block owns rows ab, ab+1) ----
        const float* hn = d_hbuf[td & 1];
        sh_h[tid >> 8][tid & 255] = __ldcg(&hn[(ab + (tid >> 8)) * 256 + (tid & 255)]);
        __syncthreads();
        {
            int qrow = tid >> 8, qcol = tid & 255;
            float q0 = 0.0f;
#pragma unroll 4
            for (int k = 0; k < 256; ++k) {
                float wq = d_WqT[k * 256 + qcol];
                q0 += sh_h[qrow][k] * wq;
            }
            sh_q[qrow][qcol] = q0;
        }
        __syncthreads();

        int r = w & 1;          // row within pair
        int ws = w >> 1;        // 0..7
        float bz = -1e30f; int bi = 0x7fffffff;
        for (int s = ws; s < 512; s += 8) {
            bool masked = (sh_mask[r][s >> 5] >> (s & 31)) & 1u;
            float lg;
            if (masked) {
                lg = MASKV;
            } else {
                const float* rp = &d_refproj[((ab + r) * 512 + s) * 256];
                float p = 0.0f;
#pragma unroll
                for (int k = lane; k < 256; k += 32)
                    p += sh_v[k] * tanhf(sh_q[r][k] + rp[k]);
                p += __shfl_xor_sync(0xffffffffu, p, 16);
                p += __shfl_xor_sync(0xffffffffu, p, 8);
                p += __shfl_xor_sync(0xffffffffu, p, 4);
                p += __shfl_xor_sync(0xffffffffu, p, 2);
                p += __shfl_xor_sync(0xffffffffu, p, 1);
                lg = p;
            }
            if (lane == 0) {
                sh_logit[r][s] = lg;
                if (!masked) {
                    float gmb = d_gumb[(td * 256 + (ab + r)) * 512 + s];
                    float z = lg + gmb;
                    if (z > bz) { bz = z; bi = s; }
                }
            }
        }
        if (lane == 0) { sh_bz[w] = bz; sh_bi[w] = bi; }
        __syncthreads();

        if (w < 2) {
            int rr = w;
            if (lane == 0) {
                float bv = -1e30f; int bidx = 0x7fffffff;
#pragma unroll
                for (int i = rr; i < 16; i += 2) {
                    if (sh_bz[i] > bv || (sh_bz[i] == bv && sh_bi[i] < bidx)) {
                        bv = sh_bz[i]; bidx = sh_bi[i];
                    }
                }
                sh_ch[rr] = bidx;
            }
            __syncwarp();
            int chosen = sh_ch[rr];
            float m = -1e30f;
            for (int s = lane; s < 512; s += 32) m = fmaxf(m, sh_logit[rr][s]);
            m = fmaxf(m, __shfl_xor_sync(0xffffffffu, m, 16));
            m = fmaxf(m, __shfl_xor_sync(0xffffffffu, m, 8));
            m = fmaxf(m, __shfl_xor_sync(0xffffffffu, m, 4));
            m = fmaxf(m, __shfl_xor_sync(0xffffffffu, m, 2));
            m = fmaxf(m, __shfl_xor_sync(0xffffffffu, m, 1));
            float es = 0.0f;
            for (int s = lane; s < 512; s += 32) es += expf(sh_logit[rr][s] - m);
            es += __shfl_xor_sync(0xffffffffu, es, 16);
            es += __shfl_xor_sync(0xffffffffu, es, 8);
            es += __shfl_xor_sync(0xffffffffu, es, 4);
            es += __shfl_xor_sync(0xffffffffu, es, 2);
            es += __shfl_xor_sync(0xffffffffu, es, 1);
            if (lane == 0) {
                int b = ab + rr;
                float lp = sh_logit[rr][chosen] - m - logf(es);
                out[b * (NSs - 1) + td] = lp;
                out[OUT_IDX_OFF + b * NSs + td + 1] = (float)chosen;
                sh_mask[rr][chosen >> 5] |= (1u << (chosen & 31));
                float2 nx;
                nx.x = inp[b * 1024 + chosen * 2];
                nx.y = inp[b * 1024 + chosen * 2 + 1];
                __stcg(&d_x2[b], nx);
            }
        }
        gridbar();
    }
}

// ---------------- host ----------------
extern "C" void kernel_launch(void* const* d_in, const int* in_sizes, int n_in,
                              void* d_out, int out_size) {
    const float* inputs  = (const float*)d_in[0];
    const float* W_embed = (const float*)d_in[1];
    const float* eWih    = (const float*)d_in[2];
    const float* eWhh    = (const float*)d_in[3];
    const float* ebih    = (const float*)d_in[4];
    const float* ebhh    = (const float*)d_in[5];
    const float* dWih    = (const float*)d_in[6];
    const float* dWhh    = (const float*)d_in[7];
    const float* dbih    = (const float*)d_in[8];
    const float* dbhh    = (const float*)d_in[9];
    const float* Wq      = (const float*)d_in[10];
    const float* Wref    = (const float*)d_in[11];
    const float* v       = (const float*)d_in[12];
    float* out = (float*)d_out;

    k_init<<<1024, 256>>>(inputs, W_embed, eWih, eWhh, ebih, ebhh,
                          dWih, dWhh, dbih, dbhh, Wq, Wref, out);
    k_gumb<<<(NSs - 1) * NBb, 512>>>();
    k_enc<<<NBLK, 512>>>(inputs);
    k_refproj<<<dim3(4, 2048), 256>>>();
    k_dec<<<NBLK, 512>>>(inputs, v, out);
}

// round 8
// speedup vs baseline: 1.2994x; 1.0444x over previous
#include <cuda_runtime.h>
#include <stdint.h>
#include <math.h>

#define NBb 256
#define NSs 512
#define MASKV  -100000.0f
#define TINYF  1.17549435e-38f
#define OUT_IDX_OFF (NBb * (NSs - 1))   // 130816
#define NBLK 128

// ---------------- device scratch (no allocations) ----------------
__device__ __align__(16) float d_encout[NBb * NSs * 256];   // (b,s,h)
__device__ __align__(16) float d_refproj[NBb * NSs * 256];  // (b,s,h)
__device__ __align__(16) float d_gumb[(NSs - 1) * NBb * NSs]; // (t,b,s) gumbel table
__device__ __align__(16) float d_WqT[256 * 256];            // [k][n] = Wq[n][k]
__device__ __align__(16) float d_WrefT[256 * 256];          // [k][n] = Wref[n][k]
__device__ __align__(16) float d_Wr_enc[256 * 1024];        // [k][j'] interleaved gates
__device__ __align__(16) float d_Wr_dec[256 * 1024];
__device__ __align__(16) float d_Ur_enc[2 * 1024];          // input-side collapsed (2 x 1024)
__device__ __align__(16) float d_Ur_dec[2 * 1024];
__device__ __align__(16) float d_bias_enc[1024];
__device__ __align__(16) float d_bias_dec[1024];
__device__ __align__(16) float d_hbuf[2][NBb * 256];
__device__ __align__(16) float d_cglob[NBb * 256];
__device__ __align__(16) float2 d_x2[NBb];
__device__ uint2 d_keys[NSs - 1];

// software grid barrier state
__device__ unsigned g_cnt = 0;
__device__ volatile unsigned g_gen = 0;

__device__ __forceinline__ void gridbar() {
    __syncthreads();
    if (threadIdx.x == 0) {
        unsigned gen = g_gen;
        __threadfence();
        if (atomicAdd(&g_cnt, 1u) == NBLK - 1) {
            g_cnt = 0;
            __threadfence();
            g_gen = gen + 1;
        } else {
            while (g_gen == gen) __nanosleep(32);
            __threadfence();
        }
    }
    __syncthreads();
}

// ---------------- threefry2x32 (exact JAX) ----------------
__device__ __forceinline__ void threefry2x32(uint32_t k0, uint32_t k1,
                                             uint32_t c0, uint32_t c1,
                                             uint32_t& o0, uint32_t& o1) {
    uint32_t ks2 = k0 ^ k1 ^ 0x1BD11BDAu;
    uint32_t x0 = c0 + k0, x1 = c1 + k1;
#define RND(r) { x0 += x1; x1 = (x1 << (r)) | (x1 >> (32 - (r))); x1 ^= x0; }
    RND(13) RND(15) RND(26) RND(6)
    x0 += k1;  x1 += ks2 + 1u;
    RND(17) RND(29) RND(16) RND(24)
    x0 += ks2; x1 += k0 + 2u;
    RND(13) RND(15) RND(26) RND(6)
    x0 += k0;  x1 += k1 + 3u;
    RND(17) RND(29) RND(16) RND(24)
    x0 += k1;  x1 += ks2 + 4u;
    RND(13) RND(15) RND(26) RND(6)
    x0 += ks2; x1 += k0 + 5u;
#undef RND
    o0 = x0; o1 = x1;
}

__device__ __forceinline__ float sigm(float x) {
    return 0.5f + 0.5f * tanhf(0.5f * x);
}

// Branchless XLA/Eigen rational tanh (the formula XLA lowers tanh to on GPU).
__device__ __forceinline__ float tanh_r(float x) {
    float xc = fminf(fmaxf(x, -7.90531110763549805f), 7.90531110763549805f);
    float x2 = xc * xc;
    float p = fmaf(x2, -2.76076847742355e-16f, 2.00018790482477e-13f);
    p = fmaf(x2, p, -8.60467152213735e-11f);
    p = fmaf(x2, p, 5.12229709037114e-08f);
    p = fmaf(x2, p, 1.48572235717979e-05f);
    p = fmaf(x2, p, 6.37261928875436e-04f);
    p = fmaf(x2, p, 4.89352455891786e-03f);
    p = xc * p;
    float q = fmaf(x2, 1.19825839466702e-06f, 1.18534705686654e-04f);
    q = fmaf(x2, q, 2.26843463243900e-03f);
    q = fmaf(x2, q, 4.89352518554385e-03f);
    return p / q;
}

// map interleaved col j' -> original gate row j
__device__ __forceinline__ int jmap(int jp) {
    int ht = jp >> 6, rem = jp & 63, hh = rem >> 2, g = rem & 3;
    return g * 256 + ht * 16 + hh;
}

// ---------------- init (weight reshapes, keys, feedback init) ----------------
__global__ void k_init(const float* __restrict__ inp, const float* __restrict__ We,
                       const float* __restrict__ eWih, const float* __restrict__ eWhh,
                       const float* __restrict__ ebih, const float* __restrict__ ebhh,
                       const float* __restrict__ dWih, const float* __restrict__ dWhh,
                       const float* __restrict__ dbih, const float* __restrict__ dbhh,
                       const float* __restrict__ Wq,  const float* __restrict__ Wref,
                       float* __restrict__ out) {
    int idx = blockIdx.x * 256 + threadIdx.x;   // 262144 threads
    if (idx < 262144) {
        int k = idx >> 10, jp = idx & 1023;
        int j = jmap(jp);
        d_Wr_enc[idx] = eWhh[j * 256 + k];
        d_Wr_dec[idx] = dWhh[j * 256 + k];
    }
    if (idx < 65536) {
        int k = idx >> 8, n = idx & 255;
        d_WqT[idx]   = Wq[n * 256 + k];
        d_WrefT[idx] = Wref[n * 256 + k];
    }
    if (idx < 2048) {
        int i = idx >> 10, jp = idx & 1023;
        int j = jmap(jp);
        float se = 0.0f, sd = 0.0f;
        for (int e = 0; e < 256; ++e) {
            float w = We[i * 256 + e];
            se += w * eWih[j * 256 + e];
            sd += w * dWih[j * 256 + e];
        }
        d_Ur_enc[idx] = se;
        d_Ur_dec[idx] = sd;
    }
    if (idx < 1024) {
        int j = jmap(idx);
        d_bias_enc[idx] = ebih[j] + ebhh[j];
        d_bias_dec[idx] = dbih[j] + dbhh[j];
    }
    if (idx < NSs - 1) {
        uint32_t o0, o1;
        threefry2x32(0u, 1u, 0u, (uint32_t)idx, o0, o1);
        d_keys[idx] = make_uint2(o0, o1);
    }
    if (idx < NBb) {
        d_x2[idx] = make_float2(inp[idx * 1024], inp[idx * 1024 + 1]);  // emb feed = inputs[b,0,:]
        out[OUT_IDX_OFF + idx * NSs] = 0.0f;                            // indices[:,0] = START
    }
}

// ---------------- precompute all gumbel noise (pure function of keys) ----------------
__global__ void k_gumb() {
    int blk = blockIdx.x;            // 0 .. 511*256-1
    int t = blk >> 8;                // step
    int b = blk & 255;               // batch row
    int s = threadIdx.x;             // 0..511
    uint2 key = d_keys[t];
    uint32_t o0, o1;
    threefry2x32(key.x, key.y, 0u, (uint32_t)(b * 512 + s), o0, o1);
    uint32_t bits = o0 ^ o1;
    float f = __uint_as_float((bits >> 9) | 0x3f800000u) - 1.0f;
    float u = fmaxf(TINYF, f + TINYF);
    d_gumb[blk * 512 + s] = -logf(-logf(u));
}

// ---------------- persistent encoder (512 threads: 1 (b,h) cell per thread) ----------------
__global__ void __launch_bounds__(512, 1) k_enc(const float* __restrict__ inp) {
    __shared__ __align__(16) float As[32][33];
    __shared__ __align__(16) float Bs[32][68];
    int tid = threadIdx.x;
    int tx = tid & 15, ty = tid >> 4;            // ty 0..31 = batch row in tile
    int bt = blockIdx.x >> 4, ht = blockIdx.x & 15;
    int b0 = bt * 32;
    int jc = ht * 64;
    int H = ht * 16 + tx;
    int brow = b0 + ty;

    float u0[4], u1[4], bb[4];
#pragma unroll
    for (int g = 0; g < 4; ++g) {
        int jp = jc + tx * 4 + g;
        u0[g] = d_Ur_enc[jp];
        u1[g] = d_Ur_enc[1024 + jp];
        bb[g] = d_bias_enc[jp];
    }
    float c0 = 0.0f;

    int a_br = tid >> 4, a_k2 = (tid & 15) * 2;
    int b_kk = tid >> 4, b_j4 = (tid & 15) * 4;

    for (int t = 0; t < 512; ++t) {
        float acc0[4] = {0, 0, 0, 0};
        if (t > 0) {
            const float* hb = d_hbuf[(t & 1) ^ 1];
            for (int kt = 0; kt < 256; kt += 32) {
                float2 a = __ldcg((const float2*)&hb[(b0 + a_br) * 256 + kt + a_k2]);
                As[a_k2 + 0][a_br] = a.x; As[a_k2 + 1][a_br] = a.y;
                *(float4*)&Bs[b_kk][b_j4] =
                    *(const float4*)&d_Wr_enc[(kt + b_kk) * 1024 + jc + b_j4];
                __syncthreads();
#pragma unroll
                for (int kk = 0; kk < 32; ++kk) {
                    float av0 = As[kk][ty];
                    float4 w = *(const float4*)&Bs[kk][tx * 4];
                    acc0[0] += av0 * w.x; acc0[1] += av0 * w.y;
                    acc0[2] += av0 * w.z; acc0[3] += av0 * w.w;
                }
                __syncthreads();
            }
        }
        float x00 = inp[brow * 1024 + t * 2], x01 = inp[brow * 1024 + t * 2 + 1];
        float g0[4];
#pragma unroll
        for (int g = 0; g < 4; ++g) {
            g0[g] = acc0[g] + bb[g] + x00 * u0[g] + x01 * u1[g];
        }
        c0 = sigm(g0[1]) * c0 + sigm(g0[0]) * tanhf(g0[2]);
        float h0v = sigm(g0[3]) * tanhf(c0);
        float* hw = d_hbuf[t & 1];
        __stcg(&hw[brow * 256 + H], h0v);
        __stcg(&d_encout[(brow * 512 + t) * 256 + H], h0v);
        gridbar();
    }
    __stcg(&d_cglob[brow * 256 + H], c0);
}

// ---------------- ref_proj = enc_out @ Wref^T  (131072 x 256 x 256) ----------------
__global__ void k_refproj() {
    __shared__ __align__(16) float As[16][68];
    __shared__ __align__(16) float Bs[16][68];
    int tid = threadIdx.x;
    int tx = tid & 15, ty = tid >> 4;
    int n0 = blockIdx.x * 64;
    int m0 = blockIdx.y * 64;
    float acc[4][4];
#pragma unroll
    for (int i = 0; i < 4; i++)
#pragma unroll
        for (int j = 0; j < 4; j++) acc[i][j] = 0.0f;

    int lm  = tid >> 2;
    int lk4 = (tid & 3) * 4;

    for (int kt = 0; kt < 16; ++kt) {
        int kb = kt * 16;
        float4 av = *reinterpret_cast<const float4*>(&d_encout[(m0 + lm) * 256 + kb + lk4]);
        As[lk4 + 0][lm] = av.x; As[lk4 + 1][lm] = av.y;
        As[lk4 + 2][lm] = av.z; As[lk4 + 3][lm] = av.w;
#pragma unroll
        for (int i = 0; i < 4; ++i) {
            int li = tid + i * 256;
            int kk = li >> 6, nn = li & 63;
            Bs[kk][nn] = d_WrefT[(kb + kk) * 256 + n0 + nn];
        }
        __syncthreads();
#pragma unroll
        for (int kk = 0; kk < 16; ++kk) {
            float4 a = *reinterpret_cast<const float4*>(&As[kk][ty * 4]);
            float4 w = *reinterpret_cast<const float4*>(&Bs[kk][tx * 4]);
            acc[0][0] += a.x * w.x; acc[0][1] += a.x * w.y; acc[0][2] += a.x * w.z; acc[0][3] += a.x * w.w;
            acc[1][0] += a.y * w.x; acc[1][1] += a.y * w.y; acc[1][2] += a.y * w.z; acc[1][3] += a.y * w.w;
            acc[2][0] += a.z * w.x; acc[2][1] += a.z * w.y; acc[2][2] += a.z * w.z; acc[2][3] += a.z * w.w;
            acc[3][0] += a.w * w.x; acc[3][1] += a.w * w.y; acc[3][2] += a.w * w.z; acc[3][3] += a.w * w.w;
        }
        __syncthreads();
    }
#pragma unroll
    for (int r = 0; r < 4; ++r) {
        float4 o = make_float4(acc[r][0], acc[r][1], acc[r][2], acc[r][3]);
        *reinterpret_cast<float4*>(&d_refproj[(m0 + ty * 4 + r) * 256 + n0 + tx * 4]) = o;
    }
}

// ---------------- persistent decoder (1024 threads / block) ----------------
__global__ void __launch_bounds__(1024, 1) k_dec(const float* __restrict__ inp,
                                                 const float* __restrict__ vvec,
                                                 float* __restrict__ out) {
    __shared__ __align__(16) float As[32][33];
    __shared__ __align__(16) float Bs[32][68];
    __shared__ float sh_h[2][256];
    __shared__ __align__(16) float sh_q[2][256];
    __shared__ __align__(16) float sh_v[256];
    __shared__ float sh_logit[2][512];
    __shared__ unsigned sh_mask[2][16];
    __shared__ float sh_bz[32];
    __shared__ int   sh_bi[32];
    __shared__ int   sh_ch[2];

    int tid = threadIdx.x;
    int tx = tid & 15, ty = (tid >> 4) & 31;   // valid for tid<512 paths
    int bt = blockIdx.x >> 4, ht = blockIdx.x & 15;
    int b0 = bt * 32;
    int jc = ht * 64;
    int H = ht * 16 + tx;
    int brow = b0 + ty;
    int ab = blockIdx.x * 2;                   // attention rows ab, ab+1
    int w = tid >> 5, lane = tid & 31;

    float u0[4], u1[4], bb[4];
#pragma unroll
    for (int g = 0; g < 4; ++g) {
        int jp = jc + tx * 4 + g;
        u0[g] = d_Ur_dec[jp];
        u1[g] = d_Ur_dec[1024 + jp];
        bb[g] = d_bias_dec[jp];
    }
    float c0 = __ldcg(&d_cglob[brow * 256 + H]);
    if (tid < 256) sh_v[tid] = vvec[tid];
    if (tid < 32) sh_mask[tid >> 4][tid & 15] = 0u;
    __syncthreads();
    if (tid < 2) sh_mask[tid][0] = 1u;   // START=0 masked
    __syncthreads();

    int a_br = tid >> 4, a_k2 = (tid & 15) * 2;
    int b_kk = tid >> 4, b_j4 = (tid & 15) * 4;

    for (int td = 0; td < 511; ++td) {
        // ---- phase A: LSTM gates (tid<512, bit-identical to round 7) ----
        float acc0[4] = {0, 0, 0, 0};
        const float* hb = d_hbuf[(td & 1) ^ 1];
        for (int kt = 0; kt < 256; kt += 32) {
            if (tid < 512) {
                float2 a = __ldcg((const float2*)&hb[(b0 + a_br) * 256 + kt + a_k2]);
                As[a_k2 + 0][a_br] = a.x; As[a_k2 + 1][a_br] = a.y;
                *(float4*)&Bs[b_kk][b_j4] =
                    *(const float4*)&d_Wr_dec[(kt + b_kk) * 1024 + jc + b_j4];
            }
            __syncthreads();
            if (tid < 512) {
#pragma unroll
                for (int kk = 0; kk < 32; ++kk) {
                    float av0 = As[kk][ty];
                    float4 ww = *(const float4*)&Bs[kk][tx * 4];
                    acc0[0] += av0 * ww.x; acc0[1] += av0 * ww.y;
                    acc0[2] += av0 * ww.z; acc0[3] += av0 * ww.w;
                }
            }
            __syncthreads();
        }
        if (tid < 512) {
            float2 xv0 = __ldcg(&d_x2[brow]);
            float g0[4];
#pragma unroll
            for (int g = 0; g < 4; ++g) {
                g0[g] = acc0[g] + bb[g] + xv0.x * u0[g] + xv0.y * u1[g];
            }
            c0 = sigm(g0[1]) * c0 + sigm(g0[0]) * tanhf(g0[2]);
            float h0v = sigm(g0[3]) * tanhf(c0);
            float* hw = d_hbuf[td & 1];
            __stcg(&hw[brow * 256 + H], h0v);
        }
        gridbar();

        // ---- phase B: q projection (tid<512, bit-identical) ----
        const float* hn = d_hbuf[td & 1];
        if (tid < 512)
            sh_h[tid >> 8][tid & 255] = __ldcg(&hn[(ab + (tid >> 8)) * 256 + (tid & 255)]);
        __syncthreads();
        if (tid < 512) {
            int qrow = tid >> 8, qcol = tid & 255;
            float q0 = 0.0f;
#pragma unroll 4
            for (int k = 0; k < 256; ++k) {
                float wq = d_WqT[k * 256 + qcol];
                q0 += sh_h[qrow][k] * wq;
            }
            sh_q[qrow][qcol] = q0;
        }
        __syncthreads();

        // ---- attention + argmax over gumbel-perturbed logits (all 32 warps) ----
        int r = w & 1;          // row within pair
        int ws = w >> 1;        // 0..15
        float bz = -1e30f; int bi = 0x7fffffff;
        const float4* q4 = (const float4*)&sh_q[r][0];
        const float4* v4 = (const float4*)&sh_v[0];
        float4 vq0 = v4[lane], vq1 = v4[32 + lane];
        float4 qq0 = q4[lane], qq1 = q4[32 + lane];
        for (int s = ws; s < 512; s += 16) {
            bool masked = (sh_mask[r][s >> 5] >> (s & 31)) & 1u;
            float lg;
            if (masked) {
                lg = MASKV;
            } else {
                const float4* rp4 = (const float4*)&d_refproj[((ab + r) * 512 + s) * 256];
                float4 a0 = rp4[lane];
                float4 a1 = rp4[32 + lane];
                float p;
                p  = vq0.x * tanh_r(qq0.x + a0.x);
                p  = fmaf(vq0.y, tanh_r(qq0.y + a0.y), p);
                p  = fmaf(vq0.z, tanh_r(qq0.z + a0.z), p);
                p  = fmaf(vq0.w, tanh_r(qq0.w + a0.w), p);
                p  = fmaf(vq1.x, tanh_r(qq1.x + a1.x), p);
                p  = fmaf(vq1.y, tanh_r(qq1.y + a1.y), p);
                p  = fmaf(vq1.z, tanh_r(qq1.z + a1.z), p);
                p  = fmaf(vq1.w, tanh_r(qq1.w + a1.w), p);
                p += __shfl_xor_sync(0xffffffffu, p, 16);
                p += __shfl_xor_sync(0xffffffffu, p, 8);
                p += __shfl_xor_sync(0xffffffffu, p, 4);
                p += __shfl_xor_sync(0xffffffffu, p, 2);
                p += __shfl_xor_sync(0xffffffffu, p, 1);
                lg = p;
            }
            if (lane == 0) {
                sh_logit[r][s] = lg;
                if (!masked) {
                    float gmb = d_gumb[(td * 256 + (ab + r)) * 512 + s];
                    float z = lg + gmb;
                    if (z > bz) { bz = z; bi = s; }
                }
            }
        }
        if (lane == 0) { sh_bz[w] = bz; sh_bi[w] = bi; }
        __syncthreads();

        if (w < 2) {
            int rr = w;
            if (lane == 0) {
                float bv = -1e30f; int bidx = 0x7fffffff;
#pragma unroll
                for (int i = rr; i < 32; i += 2) {
                    if (sh_bz[i] > bv || (sh_bz[i] == bv && sh_bi[i] < bidx)) {
                        bv = sh_bz[i]; bidx = sh_bi[i];
                    }
                }
                sh_ch[rr] = bidx;
            }
            __syncwarp();
            int chosen = sh_ch[rr];
            float m = -1e30f;
            for (int s = lane; s < 512; s += 32) m = fmaxf(m, sh_logit[rr][s]);
            m = fmaxf(m, __shfl_xor_sync(0xffffffffu, m, 16));
            m = fmaxf(m, __shfl_xor_sync(0xffffffffu, m, 8));
            m = fmaxf(m, __shfl_xor_sync(0xffffffffu, m, 4));
            m = fmaxf(m, __shfl_xor_sync(0xffffffffu, m, 2));
            m = fmaxf(m, __shfl_xor_sync(0xffffffffu, m, 1));
            float es = 0.0f;
            for (int s = lane; s < 512; s += 32) es += expf(sh_logit[rr][s] - m);
            es += __shfl_xor_sync(0xffffffffu, es, 16);
            es += __shfl_xor_sync(0xffffffffu, es, 8);
            es += __shfl_xor_sync(0xffffffffu, es, 4);
            es += __shfl_xor_sync(0xffffffffu, es, 2);
            es += __shfl_xor_sync(0xffffffffu, es, 1);
            if (lane == 0) {
                int b = ab + rr;
                float lp = sh_logit[rr][chosen] - m - logf(es);
                out[b * (NSs - 1) + td] = lp;
                out[OUT_IDX_OFF + b * NSs + td + 1] = (float)chosen;
                sh_mask[rr][chosen >> 5] |= (1u << (chosen & 31));
                float2 nx;
                nx.x = inp[b * 1024 + chosen * 2];
                nx.y = inp[b * 1024 + chosen * 2 + 1];
                __stcg(&d_x2[b], nx);
            }
        }
        gridbar();
    }
}

// ---------------- host ----------------
extern "C" void kernel_launch(void* const* d_in, const int* in_sizes, int n_in,
                              void* d_out, int out_size) {
    const float* inputs  = (const float*)d_in[0];
    const float* W_embed = (const float*)d_in[1];
    const float* eWih    = (const float*)d_in[2];
    const float* eWhh    = (const float*)d_in[3];
    const float* ebih    = (const float*)d_in[4];
    const float* ebhh    = (const float*)d_in[5];
    const float* dWih    = (const float*)d_in[6];
    const float* dWhh    = (const float*)d_in[7];
    const float* dbih    = (const float*)d_in[8];
    const float* dbhh    = (const float*)d_in[9];
    const float* Wq      = (const float*)d_in[10];
    const float* Wref    = (const float*)d_in[11];
    const float* v       = (const float*)d_in[12];
    float* out = (float*)d_out;

    k_init<<<1024, 256>>>(inputs, W_embed, eWih, eWhh, ebih, ebhh,
                          dWih, dWhh, dbih, dbhh, Wq, Wref, out);
    k_gumb<<<(NSs - 1) * NBb, 512>>>();
    k_enc<<<NBLK, 512>>>(inputs);
    k_refproj<<<dim3(4, 2048), 256>>>();
    k_dec<<<NBLK, 1024>>>(inputs, v, out);
}

// round 9
// speedup vs baseline: 1.7477x; 1.3449x over previous
#include <cuda_runtime.h>
#include <stdint.h>
#include <math.h>

#define NBb 256
#define NSs 512
#define MASKV  -100000.0f
#define TINYF  1.17549435e-38f
#define OUT_IDX_OFF (NBb * (NSs - 1))   // 130816
#define NBLK 128
#define DSMEM_BYTES ((16384 + 8192) * 4)   // sW (256x64) + hA (32x256)

// ---------------- device scratch (no allocations) ----------------
__device__ __align__(16) float d_encout[NBb * NSs * 256];   // (b,s,h)
__device__ __align__(16) float d_refproj[NBb * NSs * 256];  // (b,s,h)
__device__ __align__(16) float d_gumb[(NSs - 1) * NBb * NSs]; // (t,b,s) gumbel table
__device__ __align__(16) float d_WqT[256 * 256];            // [k][n] = Wq[n][k]
__device__ __align__(16) float d_WrefT[256 * 256];          // [k][n] = Wref[n][k]
__device__ __align__(16) float d_Wr_enc[256 * 1024];        // [k][j'] interleaved gates
__device__ __align__(16) float d_Wr_dec[256 * 1024];
__device__ __align__(16) float d_Ur_enc[2 * 1024];          // input-side collapsed (2 x 1024)
__device__ __align__(16) float d_Ur_dec[2 * 1024];
__device__ __align__(16) float d_bias_enc[1024];
__device__ __align__(16) float d_bias_dec[1024];
__device__ __align__(16) float d_hbuf[2][NBb * 256];
__device__ __align__(16) float d_cglob[NBb * 256];
__device__ __align__(16) float2 d_x2[NBb];
__device__ uint2 d_keys[NSs - 1];
__device__ int d_dummy_sink;

// software grid barrier state
__device__ unsigned g_cnt = 0;
__device__ volatile unsigned g_gen = 0;

__device__ __forceinline__ void gridbar() {
    __syncthreads();
    if (threadIdx.x == 0) {
        unsigned gen = g_gen;
        __threadfence();
        if (atomicAdd(&g_cnt, 1u) == NBLK - 1) {
            g_cnt = 0;
            __threadfence();
            g_gen = gen + 1;
        } else {
            while (g_gen == gen) __nanosleep(32);
            __threadfence();
        }
    }
    __syncthreads();
}

// ---------------- threefry2x32 (exact JAX) ----------------
__device__ __forceinline__ void threefry2x32(uint32_t k0, uint32_t k1,
                                             uint32_t c0, uint32_t c1,
                                             uint32_t& o0, uint32_t& o1) {
    uint32_t ks2 = k0 ^ k1 ^ 0x1BD11BDAu;
    uint32_t x0 = c0 + k0, x1 = c1 + k1;
#define RND(r) { x0 += x1; x1 = (x1 << (r)) | (x1 >> (32 - (r))); x1 ^= x0; }
    RND(13) RND(15) RND(26) RND(6)
    x0 += k1;  x1 += ks2 + 1u;
    RND(17) RND(29) RND(16) RND(24)
    x0 += ks2; x1 += k0 + 2u;
    RND(13) RND(15) RND(26) RND(6)
    x0 += k0;  x1 += k1 + 3u;
    RND(17) RND(29) RND(16) RND(24)
    x0 += k1;  x1 += ks2 + 4u;
    RND(13) RND(15) RND(26) RND(6)
    x0 += ks2; x1 += k0 + 5u;
#undef RND
    o0 = x0; o1 = x1;
}

__device__ __forceinline__ float sigm(float x) {
    return 0.5f + 0.5f * tanhf(0.5f * x);
}

// Branchless XLA/Eigen rational tanh, fast (approx) division.
__device__ __forceinline__ float tanh_r(float x) {
    float xc = fminf(fmaxf(x, -7.90531110763549805f), 7.90531110763549805f);
    float x2 = xc * xc;
    float p = fmaf(x2, -2.76076847742355e-16f, 2.00018790482477e-13f);
    p = fmaf(x2, p, -8.60467152213735e-11f);
    p = fmaf(x2, p, 5.12229709037114e-08f);
    p = fmaf(x2, p, 1.48572235717979e-05f);
    p = fmaf(x2, p, 6.37261928875436e-04f);
    p = fmaf(x2, p, 4.89352455891786e-03f);
    p = xc * p;
    float q = fmaf(x2, 1.19825839466702e-06f, 1.18534705686654e-04f);
    q = fmaf(x2, q, 2.26843463243900e-03f);
    q = fmaf(x2, q, 4.89352518554385e-03f);
    return __fdividef(p, q);
}

// map interleaved col j' -> original gate row j
__device__ __forceinline__ int jmap(int jp) {
    int ht = jp >> 6, rem = jp & 63, hh = rem >> 2, g = rem & 3;
    return g * 256 + ht * 16 + hh;
}

// ---------------- init (weight reshapes, keys, feedback init) ----------------
__global__ void k_init(const float* __restrict__ inp, const float* __restrict__ We,
                       const float* __restrict__ eWih, const float* __restrict__ eWhh,
                       const float* __restrict__ ebih, const float* __restrict__ ebhh,
                       const float* __restrict__ dWih, const float* __restrict__ dWhh,
                       const float* __restrict__ dbih, const float* __restrict__ dbhh,
                       const float* __restrict__ Wq,  const float* __restrict__ Wref,
                       float* __restrict__ out) {
    int idx = blockIdx.x * 256 + threadIdx.x;   // 262144 threads
    if (idx < 262144) {
        int k = idx >> 10, jp = idx & 1023;
        int j = jmap(jp);
        d_Wr_enc[idx] = eWhh[j * 256 + k];
        d_Wr_dec[idx] = dWhh[j * 256 + k];
    }
    if (idx < 65536) {
        int k = idx >> 8, n = idx & 255;
        d_WqT[idx]   = Wq[n * 256 + k];
        d_WrefT[idx] = Wref[n * 256 + k];
    }
    if (idx < 2048) {
        int i = idx >> 10, jp = idx & 1023;
        int j = jmap(jp);
        float se = 0.0f, sd = 0.0f;
        for (int e = 0; e < 256; ++e) {
            float w = We[i * 256 + e];
            se += w * eWih[j * 256 + e];
            sd += w * dWih[j * 256 + e];
        }
        d_Ur_enc[idx] = se;
        d_Ur_dec[idx] = sd;
    }
    if (idx < 1024) {
        int j = jmap(idx);
        d_bias_enc[idx] = ebih[j] + ebhh[j];
        d_bias_dec[idx] = dbih[j] + dbhh[j];
    }
    if (idx < NSs - 1) {
        uint32_t o0, o1;
        threefry2x32(0u, 1u, 0u, (uint32_t)idx, o0, o1);
        d_keys[idx] = make_uint2(o0, o1);
    }
    if (idx < NBb) {
        d_x2[idx] = make_float2(inp[idx * 1024], inp[idx * 1024 + 1]);  // emb feed = inputs[b,0,:]
        out[OUT_IDX_OFF + idx * NSs] = 0.0f;                            // indices[:,0] = START
    }
}

// ---------------- precompute all gumbel noise (pure function of keys) ----------------
__global__ void k_gumb() {
    int blk = blockIdx.x;            // 0 .. 511*256-1
    int t = blk >> 8;                // step
    int b = blk & 255;               // batch row
    int s = threadIdx.x;             // 0..511
    uint2 key = d_keys[t];
    uint32_t o0, o1;
    threefry2x32(key.x, key.y, 0u, (uint32_t)(b * 512 + s), o0, o1);
    uint32_t bits = o0 ^ o1;
    float f = __uint_as_float((bits >> 9) | 0x3f800000u) - 1.0f;
    float u = fmaxf(TINYF, f + TINYF);
    d_gumb[blk * 512 + s] = -logf(-logf(u));
}

// no-op spacer so ncu's "-s 5 -c 1" capture slot lands on k_dec
__global__ void k_dummy() { if (threadIdx.x == 0) d_dummy_sink = 1; }

// ---------------- persistent encoder (512 threads: 1 (b,h) cell per thread) ----------------
__global__ void __launch_bounds__(512, 1) k_enc(const float* __restrict__ inp) {
    extern __shared__ __align__(16) float dsm[];
    float* sW = dsm;            // [k*64 + jj]  (64 KB, resident all steps)
    float* hA = dsm + 16384;    // [r*256 + k]  (32 KB, reloaded per step)

    int tid = threadIdx.x;
    int tx = tid & 15, ty = tid >> 4;            // ty 0..31 = batch row in tile
    int bt = blockIdx.x >> 4, ht = blockIdx.x & 15;
    int b0 = bt * 32;
    int jc = ht * 64;
    int H = ht * 16 + tx;
    int brow = b0 + ty;

    // preload weight slice once
    for (int i = tid; i < 16384; i += 512)
        sW[i] = d_Wr_enc[(i >> 6) * 1024 + jc + (i & 63)];

    float u0[4], u1[4], bb[4];
#pragma unroll
    for (int g = 0; g < 4; ++g) {
        int jp = jc + tx * 4 + g;
        u0[g] = d_Ur_enc[jp];
        u1[g] = d_Ur_enc[1024 + jp];
        bb[g] = d_bias_enc[jp];
    }
    float c0 = 0.0f;
    __syncthreads();

    for (int t = 0; t < 512; ++t) {
        float acc0[4] = {0, 0, 0, 0};
        if (t > 0) {
            const float* hb = d_hbuf[(t & 1) ^ 1];
            for (int i = tid * 4; i < 8192; i += 512 * 4)
                *(float4*)&hA[i] = __ldcg((const float4*)&hb[b0 * 256 + i]);
            __syncthreads();
#pragma unroll 8
            for (int k = 0; k < 256; ++k) {
                float a = hA[ty * 256 + k];
                float4 w = *(const float4*)&sW[k * 64 + tx * 4];
                acc0[0] += a * w.x; acc0[1] += a * w.y;
                acc0[2] += a * w.z; acc0[3] += a * w.w;
            }
        }
        float x00 = inp[brow * 1024 + t * 2], x01 = inp[brow * 1024 + t * 2 + 1];
        float g0[4];
#pragma unroll
        for (int g = 0; g < 4; ++g) {
            g0[g] = acc0[g] + bb[g] + x00 * u0[g] + x01 * u1[g];
        }
        c0 = sigm(g0[1]) * c0 + sigm(g0[0]) * tanhf(g0[2]);
        float h0v = sigm(g0[3]) * tanhf(c0);
        float* hw = d_hbuf[t & 1];
        __stcg(&hw[brow * 256 + H], h0v);
        __stcg(&d_encout[(brow * 512 + t) * 256 + H], h0v);
        gridbar();
    }
    __stcg(&d_cglob[brow * 256 + H], c0);
}

// ---------------- ref_proj = enc_out @ Wref^T  (131072 x 256 x 256) ----------------
__global__ void k_refproj() {
    __shared__ __align__(16) float As[16][68];
    __shared__ __align__(16) float Bs[16][68];
    int tid = threadIdx.x;
    int tx = tid & 15, ty = tid >> 4;
    int n0 = blockIdx.x * 64;
    int m0 = blockIdx.y * 64;
    float acc[4][4];
#pragma unroll
    for (int i = 0; i < 4; i++)
#pragma unroll
        for (int j = 0; j < 4; j++) acc[i][j] = 0.0f;

    int lm  = tid >> 2;
    int lk4 = (tid & 3) * 4;

    for (int kt = 0; kt < 16; ++kt) {
        int kb = kt * 16;
        float4 av = *reinterpret_cast<const float4*>(&d_encout[(m0 + lm) * 256 + kb + lk4]);
        As[lk4 + 0][lm] = av.x; As[lk4 + 1][lm] = av.y;
        As[lk4 + 2][lm] = av.z; As[lk4 + 3][lm] = av.w;
#pragma unroll
        for (int i = 0; i < 4; ++i) {
            int li = tid + i * 256;
            int kk = li >> 6, nn = li & 63;
            Bs[kk][nn] = d_WrefT[(kb + kk) * 256 + n0 + nn];
        }
        __syncthreads();
#pragma unroll
        for (int kk = 0; kk < 16; ++kk) {
            float4 a = *reinterpret_cast<const float4*>(&As[kk][ty * 4]);
            float4 w = *reinterpret_cast<const float4*>(&Bs[kk][tx * 4]);
            acc[0][0] += a.x * w.x; acc[0][1] += a.x * w.y; acc[0][2] += a.x * w.z; acc[0][3] += a.x * w.w;
            acc[1][0] += a.y * w.x; acc[1][1] += a.y * w.y; acc[1][2] += a.y * w.z; acc[1][3] += a.y * w.w;
            acc[2][0] += a.z * w.x; acc[2][1] += a.z * w.y; acc[2][2] += a.z * w.z; acc[2][3] += a.z * w.w;
            acc[3][0] += a.w * w.x; acc[3][1] += a.w * w.y; acc[3][2] += a.w * w.z; acc[3][3] += a.w * w.w;
        }
        __syncthreads();
    }
#pragma unroll
    for (int r = 0; r < 4; ++r) {
        float4 o = make_float4(acc[r][0], acc[r][1], acc[r][2], acc[r][3]);
        *reinterpret_cast<float4*>(&d_refproj[(m0 + ty * 4 + r) * 256 + n0 + tx * 4]) = o;
    }
}

// ---------------- persistent decoder (1024 threads / block) ----------------
__global__ void __launch_bounds__(1024, 1) k_dec(const float* __restrict__ inp,
                                                 const float* __restrict__ vvec,
                                                 float* __restrict__ out) {
    extern __shared__ __align__(16) float dsm[];
    float* sW = dsm;            // [k*64 + jj]
    float* hA = dsm + 16384;    // [r*256 + k]

    __shared__ float sh_h[2][256];
    __shared__ __align__(16) float sh_q[2][256];
    __shared__ __align__(16) float sh_v[256];
    __shared__ float sh_logit[2][512];
    __shared__ unsigned sh_mask[2][16];
    __shared__ float sh_bz[32];
    __shared__ int   sh_bi[32];
    __shared__ int   sh_ch[2];

    int tid = threadIdx.x;
    int tx = tid & 15, ty = (tid >> 4) & 31;   // valid for tid<512 paths
    int bt = blockIdx.x >> 4, ht = blockIdx.x & 15;
    int b0 = bt * 32;
    int jc = ht * 64;
    int H = ht * 16 + tx;
    int brow = b0 + ty;
    int ab = blockIdx.x * 2;                   // attention rows ab, ab+1
    int w = tid >> 5, lane = tid & 31;

    // preload weight slice once (all 1024 threads)
    for (int i = tid; i < 16384; i += 1024)
        sW[i] = d_Wr_dec[(i >> 6) * 1024 + jc + (i & 63)];

    float u0[4], u1[4], bb[4];
#pragma unroll
    for (int g = 0; g < 4; ++g) {
        int jp = jc + tx * 4 + g;
        u0[g] = d_Ur_dec[jp];
        u1[g] = d_Ur_dec[1024 + jp];
        bb[g] = d_bias_dec[jp];
    }
    float c0 = __ldcg(&d_cglob[brow * 256 + H]);
    if (tid < 256) sh_v[tid] = vvec[tid];
    if (tid < 32) sh_mask[tid >> 4][tid & 15] = 0u;
    __syncthreads();
    if (tid < 2) sh_mask[tid][0] = 1u;   // START=0 masked
    __syncthreads();

    for (int td = 0; td < 511; ++td) {
        // ---- phase A: LSTM gates (GEMM on tid<512, bit-identical k-order) ----
        const float* hb = d_hbuf[(td & 1) ^ 1];
        for (int i = tid * 4; i < 8192; i += 1024 * 4)
            *(float4*)&hA[i] = __ldcg((const float4*)&hb[b0 * 256 + i]);
        __syncthreads();
        if (tid < 512) {
            float acc0[4] = {0, 0, 0, 0};
#pragma unroll 8
            for (int k = 0; k < 256; ++k) {
                float a = hA[ty * 256 + k];
                float4 ww = *(const float4*)&sW[k * 64 + tx * 4];
                acc0[0] += a * ww.x; acc0[1] += a * ww.y;
                acc0[2] += a * ww.z; acc0[3] += a * ww.w;
            }
            float2 xv0 = __ldcg(&d_x2[brow]);
            float g0[4];
#pragma unroll
            for (int g = 0; g < 4; ++g) {
                g0[g] = acc0[g] + bb[g] + xv0.x * u0[g] + xv0.y * u1[g];
            }
            c0 = sigm(g0[1]) * c0 + sigm(g0[0]) * tanhf(g0[2]);
            float h0v = sigm(g0[3]) * tanhf(c0);
            float* hw = d_hbuf[td & 1];
            __stcg(&hw[brow * 256 + H], h0v);
        }
        gridbar();

        // ---- phase B: q projection (tid<512, bit-identical sum order) ----
        const float* hn = d_hbuf[td & 1];
        if (tid < 512)
            sh_h[tid >> 8][tid & 255] = __ldcg(&hn[(ab + (tid >> 8)) * 256 + (tid & 255)]);
        __syncthreads();
        if (tid < 512) {
            int qrow = tid >> 8, qcol = tid & 255;
            float q0 = 0.0f;
#pragma unroll 16
            for (int k = 0; k < 256; ++k) {
                float wq = d_WqT[k * 256 + qcol];
                q0 += sh_h[qrow][k] * wq;
            }
            sh_q[qrow][qcol] = q0;
        }
        __syncthreads();

        // ---- attention + argmax over gumbel-perturbed logits (all 32 warps) ----
        int r = w & 1;          // row within pair
        int ws = w >> 1;        // 0..15
        float bz = -1e30f; int bi = 0x7fffffff;
        const float4* q4 = (const float4*)&sh_q[r][0];
        const float4* v4 = (const float4*)&sh_v[0];
        float4 vq0 = v4[lane], vq1 = v4[32 + lane];
        float4 qq0 = q4[lane], qq1 = q4[32 + lane];
        for (int s = ws; s < 512; s += 16) {
            bool masked = (sh_mask[r][s >> 5] >> (s & 31)) & 1u;
            float lg;
            if (masked) {
                lg = MASKV;
            } else {
                const float4* rp4 = (const float4*)&d_refproj[((ab + r) * 512 + s) * 256];
                float4 a0 = rp4[lane];
                float4 a1 = rp4[32 + lane];
                float p;
                p  = vq0.x * tanh_r(qq0.x + a0.x);
                p  = fmaf(vq0.y, tanh_r(qq0.y + a0.y), p);
                p  = fmaf(vq0.z, tanh_r(qq0.z + a0.z), p);
                p  = fmaf(vq0.w, tanh_r(qq0.w + a0.w), p);
                p  = fmaf(vq1.x, tanh_r(qq1.x + a1.x), p);
                p  = fmaf(vq1.y, tanh_r(qq1.y + a1.y), p);
                p  = fmaf(vq1.z, tanh_r(qq1.z + a1.z), p);
                p  = fmaf(vq1.w, tanh_r(qq1.w + a1.w), p);
                p += __shfl_xor_sync(0xffffffffu, p, 16);
                p += __shfl_xor_sync(0xffffffffu, p, 8);
                p += __shfl_xor_sync(0xffffffffu, p, 4);
                p += __shfl_xor_sync(0xffffffffu, p, 2);
                p += __shfl_xor_sync(0xffffffffu, p, 1);
                lg = p;
            }
            if (lane == 0) {
                sh_logit[r][s] = lg;
                if (!masked) {
                    float gmb = d_gumb[(td * 256 + (ab + r)) * 512 + s];
                    float z = lg + gmb;
                    if (z > bz) { bz = z; bi = s; }
                }
            }
        }
        if (lane == 0) { sh_bz[w] = bz; sh_bi[w] = bi; }
        __syncthreads();

        if (w < 2) {
            int rr = w;
            if (lane == 0) {
                float bv = -1e30f; int bidx = 0x7fffffff;
#pragma unroll
                for (int i = rr; i < 32; i += 2) {
                    if (sh_bz[i] > bv || (sh_bz[i] == bv && sh_bi[i] < bidx)) {
                        bv = sh_bz[i]; bidx = sh_bi[i];
                    }
                }
                sh_ch[rr] = bidx;
            }
            __syncwarp();
            int chosen = sh_ch[rr];
            float m = -1e30f;
            for (int s = lane; s < 512; s += 32) m = fmaxf(m, sh_logit[rr][s]);
            m = fmaxf(m, __shfl_xor_sync(0xffffffffu, m, 16));
            m = fmaxf(m, __shfl_xor_sync(0xffffffffu, m, 8));
            m = fmaxf(m, __shfl_xor_sync(0xffffffffu, m, 4));
            m = fmaxf(m, __shfl_xor_sync(0xffffffffu, m, 2));
            m = fmaxf(m, __shfl_xor_sync(0xffffffffu, m, 1));
            float es = 0.0f;
            for (int s = lane; s < 512; s += 32) es += expf(sh_logit[rr][s] - m);
            es += __shfl_xor_sync(0xffffffffu, es, 16);
            es += __shfl_xor_sync(0xffffffffu, es, 8);
            es += __shfl_xor_sync(0xffffffffu, es, 4);
            es += __shfl_xor_sync(0xffffffffu, es, 2);
            es += __shfl_xor_sync(0xffffffffu, es, 1);
            if (lane == 0) {
                int b = ab + rr;
                float lp = sh_logit[rr][chosen] - m - logf(es);
                out[b * (NSs - 1) + td] = lp;
                out[OUT_IDX_OFF + b * NSs + td + 1] = (float)chosen;
                sh_mask[rr][chosen >> 5] |= (1u << (chosen & 31));
                float2 nx;
                nx.x = inp[b * 1024 + chosen * 2];
                nx.y = inp[b * 1024 + chosen * 2 + 1];
                __stcg(&d_x2[b], nx);
            }
        }
        gridbar();
    }
}

// ---------------- host ----------------
extern "C" void kernel_launch(void* const* d_in, const int* in_sizes, int n_in,
                              void* d_out, int out_size) {
    const float* inputs  = (const float*)d_in[0];
    const float* W_embed = (const float*)d_in[1];
    const float* eWih    = (const float*)d_in[2];
    const float* eWhh    = (const float*)d_in[3];
    const float* ebih    = (const float*)d_in[4];
    const float* ebhh    = (const float*)d_in[5];
    const float* dWih    = (const float*)d_in[6];
    const float* dWhh    = (const float*)d_in[7];
    const float* dbih    = (const float*)d_in[8];
    const float* dbhh    = (const float*)d_in[9];
    const float* Wq      = (const float*)d_in[10];
    const float* Wref    = (const float*)d_in[11];
    const float* v       = (const float*)d_in[12];
    float* out = (float*)d_out;

    static int attr_done = 0;
    if (!attr_done) {
        cudaFuncSetAttribute(k_enc, cudaFuncAttributeMaxDynamicSharedMemorySize, DSMEM_BYTES);
        cudaFuncSetAttribute(k_dec, cudaFuncAttributeMaxDynamicSharedMemorySize, DSMEM_BYTES);
        attr_done = 1;
    }

    k_init<<<1024, 256>>>(inputs, W_embed, eWih, eWhh, ebih, ebhh,
                          dWih, dWhh, dbih, dbhh, Wq, Wref, out);
    k_gumb<<<(NSs - 1) * NBb, 512>>>();
    k_enc<<<NBLK, 512, DSMEM_BYTES>>>(inputs);
    k_dummy<<<1, 32>>>();
    k_refproj<<<dim3(4, 2048), 256>>>();
    k_dec<<<NBLK, 1024, DSMEM_BYTES>>>(inputs, v, out);
}

// round 10
// speedup vs baseline: 1.9716x; 1.1281x over previous
#include <cuda_runtime.h>
#include <stdint.h>
#include <math.h>

#define NBb 256
#define NSs 512
#define MASKV  -100000.0f
#define TINYF  1.17549435e-38f
#define OUT_IDX_OFF (NBb * (NSs - 1))   // 130816
#define NBLK 128
#define DSMEM_BYTES ((16384 + 8192) * 4)   // sW (256x64) + hA (32x256)

// ---------------- device scratch (no allocations) ----------------
__device__ __align__(16) float d_encout[NBb * NSs * 256];   // (b,s,h)
__device__ __align__(16) float d_refproj[NBb * NSs * 256];  // (b,s,h)
__device__ __align__(16) float d_gumb[(NSs - 1) * NBb * NSs]; // (t,b,s) gumbel table
__device__ __align__(16) float d_WqT[256 * 256];            // [k][n] = Wq[n][k]
__device__ __align__(16) float d_WrefT[256 * 256];          // [k][n] = Wref[n][k]
__device__ __align__(16) float d_Wr_enc[256 * 1024];        // [k][j'] interleaved gates
__device__ __align__(16) float d_Wr_dec[256 * 1024];
__device__ __align__(16) float d_Ur_enc[2 * 1024];          // input-side collapsed (2 x 1024)
__device__ __align__(16) float d_Ur_dec[2 * 1024];
__device__ __align__(16) float d_bias_enc[1024];
__device__ __align__(16) float d_bias_dec[1024];
__device__ __align__(16) float d_hbuf[2][NBb * 256];
__device__ __align__(16) float d_cglob[NBb * 256];
__device__ __align__(16) float2 d_x2[NBb];

// software grid barrier state
__device__ unsigned g_cnt = 0;
__device__ volatile unsigned g_gen = 0;

__device__ __forceinline__ void gridbar() {
    __syncthreads();
    if (threadIdx.x == 0) {
        unsigned gen = g_gen;
        __threadfence();
        if (atomicAdd(&g_cnt, 1u) == NBLK - 1) {
            g_cnt = 0;
            __threadfence();
            g_gen = gen + 1;
        } else {
            while (g_gen == gen) __nanosleep(32);
            __threadfence();
        }
    }
    __syncthreads();
}

// ---------------- threefry2x32 (exact JAX) ----------------
__device__ __forceinline__ void threefry2x32(uint32_t k0, uint32_t k1,
                                             uint32_t c0, uint32_t c1,
                                             uint32_t& o0, uint32_t& o1) {
    uint32_t ks2 = k0 ^ k1 ^ 0x1BD11BDAu;
    uint32_t x0 = c0 + k0, x1 = c1 + k1;
#define RND(r) { x0 += x1; x1 = (x1 << (r)) | (x1 >> (32 - (r))); x1 ^= x0; }
    RND(13) RND(15) RND(26) RND(6)
    x0 += k1;  x1 += ks2 + 1u;
    RND(17) RND(29) RND(16) RND(24)
    x0 += ks2; x1 += k0 + 2u;
    RND(13) RND(15) RND(26) RND(6)
    x0 += k0;  x1 += k1 + 3u;
    RND(17) RND(29) RND(16) RND(24)
    x0 += k1;  x1 += ks2 + 4u;
    RND(13) RND(15) RND(26) RND(6)
    x0 += ks2; x1 += k0 + 5u;
#undef RND
    o0 = x0; o1 = x1;
}

__device__ __forceinline__ float sigm(float x) {
    return 0.5f + 0.5f * tanhf(0.5f * x);
}

// Branchless XLA/Eigen rational tanh, fast (approx) division.
__device__ __forceinline__ float tanh_r(float x) {
    float xc = fminf(fmaxf(x, -7.90531110763549805f), 7.90531110763549805f);
    float x2 = xc * xc;
    float p = fmaf(x2, -2.76076847742355e-16f, 2.00018790482477e-13f);
    p = fmaf(x2, p, -8.60467152213735e-11f);
    p = fmaf(x2, p, 5.12229709037114e-08f);
    p = fmaf(x2, p, 1.48572235717979e-05f);
    p = fmaf(x2, p, 6.37261928875436e-04f);
    p = fmaf(x2, p, 4.89352455891786e-03f);
    p = xc * p;
    float q = fmaf(x2, 1.19825839466702e-06f, 1.18534705686654e-04f);
    q = fmaf(x2, q, 2.26843463243900e-03f);
    q = fmaf(x2, q, 4.89352518554385e-03f);
    return __fdividef(p, q);
}

// map interleaved col j' -> original gate row j
__device__ __forceinline__ int jmap(int jp) {
    int ht = jp >> 6, rem = jp & 63, hh = rem >> 2, g = rem & 3;
    return g * 256 + ht * 16 + hh;
}

// ---------------- init + gumbel table (one kernel; launch index 0) ----------------
// grid: 130816 blocks x 512 threads. Gumbel part: block = (t,b), thread = s.
// Init parts guarded by global idx.
__global__ void k_init(const float* __restrict__ inp, const float* __restrict__ We,
                       const float* __restrict__ eWih, const float* __restrict__ eWhh,
                       const float* __restrict__ ebih, const float* __restrict__ ebhh,
                       const float* __restrict__ dWih, const float* __restrict__ dWhh,
                       const float* __restrict__ dbih, const float* __restrict__ dbhh,
                       const float* __restrict__ Wq,  const float* __restrict__ Wref,
                       float* __restrict__ out) {
    __shared__ uint2 skey;
    int blk = blockIdx.x;
    int t = blk >> 8;                // step 0..510
    int b = blk & 255;               // batch row
    int s = threadIdx.x;             // 0..511
    if (threadIdx.x == 0) {
        uint32_t o0, o1;
        threefry2x32(0u, 1u, 0u, (uint32_t)t, o0, o1);   // split of key(1)=(0,1)
        skey = make_uint2(o0, o1);
    }
    __syncthreads();
    {
        uint32_t o0, o1;
        threefry2x32(skey.x, skey.y, 0u, (uint32_t)(b * 512 + s), o0, o1);
        uint32_t bits = o0 ^ o1;
        float f = __uint_as_float((bits >> 9) | 0x3f800000u) - 1.0f;
        float u = fmaxf(TINYF, f + TINYF);
        d_gumb[blk * 512 + s] = -logf(-logf(u));
    }

    long long gidx = (long long)blk * 512 + s;
    if (gidx >= 262144) return;
    int idx = (int)gidx;
    {
        int k = idx >> 10, jp = idx & 1023;
        int j = jmap(jp);
        d_Wr_enc[idx] = eWhh[j * 256 + k];
        d_Wr_dec[idx] = dWhh[j * 256 + k];
    }
    if (idx < 65536) {
        int k = idx >> 8, n = idx & 255;
        d_WqT[idx]   = Wq[n * 256 + k];
        d_WrefT[idx] = Wref[n * 256 + k];
    }
    if (idx < 2048) {
        int i = idx >> 10, jp = idx & 1023;
        int j = jmap(jp);
        float se = 0.0f, sd = 0.0f;
        for (int e = 0; e < 256; ++e) {
            float w = We[i * 256 + e];
            se += w * eWih[j * 256 + e];
            sd += w * dWih[j * 256 + e];
        }
        d_Ur_enc[idx] = se;
        d_Ur_dec[idx] = sd;
    }
    if (idx < 1024) {
        int j = jmap(idx);
        d_bias_enc[idx] = ebih[j] + ebhh[j];
        d_bias_dec[idx] = dbih[j] + dbhh[j];
    }
    if (idx < NBb) {
        d_x2[idx] = make_float2(inp[idx * 1024], inp[idx * 1024 + 1]);  // emb feed = inputs[b,0,:]
        out[OUT_IDX_OFF + idx * NSs] = 0.0f;                            // indices[:,0] = START
    }
}

// ---------------- persistent encoder (512 threads: 1 (b,h) cell per thread) ----------------
__global__ void __launch_bounds__(512, 1) k_enc(const float* __restrict__ inp) {
    extern __shared__ __align__(16) float dsm[];
    float* sW = dsm;            // [k*64 + jj]  (64 KB, resident all steps)
    float* hA = dsm + 16384;    // [r*256 + k]  (32 KB, reloaded per step)

    int tid = threadIdx.x;
    int tx = tid & 15, ty = tid >> 4;            // ty 0..31 = batch row in tile
    int bt = blockIdx.x >> 4, ht = blockIdx.x & 15;
    int b0 = bt * 32;
    int jc = ht * 64;
    int H = ht * 16 + tx;
    int brow = b0 + ty;

    // preload weight slice once
    for (int i = tid; i < 16384; i += 512)
        sW[i] = d_Wr_enc[(i >> 6) * 1024 + jc + (i & 63)];

    float u0[4], u1[4], bb[4];
#pragma unroll
    for (int g = 0; g < 4; ++g) {
        int jp = jc + tx * 4 + g;
        u0[g] = d_Ur_enc[jp];
        u1[g] = d_Ur_enc[1024 + jp];
        bb[g] = d_bias_enc[jp];
    }
    float c0 = 0.0f;
    __syncthreads();

    for (int t = 0; t < 512; ++t) {
        float acc0[4] = {0, 0, 0, 0};
        if (t > 0) {
            const float* hb = d_hbuf[(t & 1) ^ 1];
            for (int i = tid * 4; i < 8192; i += 512 * 4)
                *(float4*)&hA[i] = __ldcg((const float4*)&hb[b0 * 256 + i]);
            __syncthreads();
#pragma unroll 8
            for (int k = 0; k < 256; ++k) {
                float a = hA[ty * 256 + k];
                float4 w = *(const float4*)&sW[k * 64 + tx * 4];
                acc0[0] += a * w.x; acc0[1] += a * w.y;
                acc0[2] += a * w.z; acc0[3] += a * w.w;
            }
        }
        float x00 = inp[brow * 1024 + t * 2], x01 = inp[brow * 1024 + t * 2 + 1];
        float g0[4];
#pragma unroll
        for (int g = 0; g < 4; ++g) {
            g0[g] = acc0[g] + bb[g] + x00 * u0[g] + x01 * u1[g];
        }
        c0 = sigm(g0[1]) * c0 + sigm(g0[0]) * tanhf(g0[2]);
        float h0v = sigm(g0[3]) * tanhf(c0);
        float* hw = d_hbuf[t & 1];
        __stcg(&hw[brow * 256 + H], h0v);
        __stcg(&d_encout[(brow * 512 + t) * 256 + H], h0v);
        gridbar();
    }
    __stcg(&d_cglob[brow * 256 + H], c0);
}

// ---------------- ref_proj = enc_out @ Wref^T  (131072 x 256 x 256) ----------------
__global__ void k_refproj() {
    __shared__ __align__(16) float As[16][68];
    __shared__ __align__(16) float Bs[16][68];
    int tid = threadIdx.x;
    int tx = tid & 15, ty = tid >> 4;
    int n0 = blockIdx.x * 64;
    int m0 = blockIdx.y * 64;
    float acc[4][4];
#pragma unroll
    for (int i = 0; i < 4; i++)
#pragma unroll
        for (int j = 0; j < 4; j++) acc[i][j] = 0.0f;

    int lm  = tid >> 2;
    int lk4 = (tid & 3) * 4;

    for (int kt = 0; kt < 16; ++kt) {
        int kb = kt * 16;
        float4 av = *reinterpret_cast<const float4*>(&d_encout[(m0 + lm) * 256 + kb + lk4]);
        As[lk4 + 0][lm] = av.x; As[lk4 + 1][lm] = av.y;
        As[lk4 + 2][lm] = av.z; As[lk4 + 3][lm] = av.w;
#pragma unroll
        for (int i = 0; i < 4; ++i) {
            int li = tid + i * 256;
            int kk = li >> 6, nn = li & 63;
            Bs[kk][nn] = d_WrefT[(kb + kk) * 256 + n0 + nn];
        }
        __syncthreads();
#pragma unroll
        for (int kk = 0; kk < 16; ++kk) {
            float4 a = *reinterpret_cast<const float4*>(&As[kk][ty * 4]);
            float4 w = *reinterpret_cast<const float4*>(&Bs[kk][tx * 4]);
            acc[0][0] += a.x * w.x; acc[0][1] += a.x * w.y; acc[0][2] += a.x * w.z; acc[0][3] += a.x * w.w;
            acc[1][0] += a.y * w.x; acc[1][1] += a.y * w.y; acc[1][2] += a.y * w.z; acc[1][3] += a.y * w.w;
            acc[2][0] += a.z * w.x; acc[2][1] += a.z * w.y; acc[2][2] += a.z * w.z; acc[2][3] += a.z * w.w;
            acc[3][0] += a.w * w.x; acc[3][1] += a.w * w.y; acc[3][2] += a.w * w.z; acc[3][3] += a.w * w.w;
        }
        __syncthreads();
    }
#pragma unroll
    for (int r = 0; r < 4; ++r) {
        float4 o = make_float4(acc[r][0], acc[r][1], acc[r][2], acc[r][3]);
        *reinterpret_cast<float4*>(&d_refproj[(m0 + ty * 4 + r) * 256 + n0 + tx * 4]) = o;
    }
}

// ---------------- persistent decoder (1024 threads / block) ----------------
__global__ void __launch_bounds__(1024, 1) k_dec(const float* __restrict__ inp,
                                                 const float* __restrict__ vvec,
                                                 float* __restrict__ out) {
    extern __shared__ __align__(16) float dsm[];
    float* sW = dsm;            // [k*64 + jj]
    float* hA = dsm + 16384;    // [r*256 + k]

    __shared__ float sh_h[2][256];
    __shared__ __align__(16) float sh_q[2][256];
    __shared__ __align__(16) float sh_v[256];
    __shared__ float sh_logit[2][512];
    __shared__ unsigned sh_mask[2][16];
    __shared__ float sh_bz[32];
    __shared__ int   sh_bi[32];
    __shared__ int   sh_ch[2];

    int tid = threadIdx.x;
    int tx = tid & 15, ty = (tid >> 4) & 31;   // valid for tid<512 paths
    int bt = blockIdx.x >> 4, ht = blockIdx.x & 15;
    int b0 = bt * 32;
    int jc = ht * 64;
    int H = ht * 16 + tx;
    int brow = b0 + ty;
    int ab = blockIdx.x * 2;                   // attention rows ab, ab+1
    int w = tid >> 5, lane = tid & 31;

    // preload weight slice once (all 1024 threads)
    for (int i = tid; i < 16384; i += 1024)
        sW[i] = d_Wr_dec[(i >> 6) * 1024 + jc + (i & 63)];

    float u0[4], u1[4], bb[4];
#pragma unroll
    for (int g = 0; g < 4; ++g) {
        int jp = jc + tx * 4 + g;
        u0[g] = d_Ur_dec[jp];
        u1[g] = d_Ur_dec[1024 + jp];
        bb[g] = d_bias_dec[jp];
    }
    float c0 = __ldcg(&d_cglob[brow * 256 + H]);
    if (tid < 256) sh_v[tid] = vvec[tid];
    if (tid < 32) sh_mask[tid >> 4][tid & 15] = 0u;
    __syncthreads();
    if (tid < 2) sh_mask[tid][0] = 1u;   // START=0 masked
    __syncthreads();

    for (int td = 0; td < 511; ++td) {
        // ---- phase A: LSTM gates (GEMM on tid<512, bit-identical k-order) ----
        const float* hb = d_hbuf[(td & 1) ^ 1];
        for (int i = tid * 4; i < 8192; i += 1024 * 4)
            *(float4*)&hA[i] = __ldcg((const float4*)&hb[b0 * 256 + i]);
        __syncthreads();
        if (tid < 512) {
            float acc0[4] = {0, 0, 0, 0};
#pragma unroll 8
            for (int k = 0; k < 256; ++k) {
                float a = hA[ty * 256 + k];
                float4 ww = *(const float4*)&sW[k * 64 + tx * 4];
                acc0[0] += a * ww.x; acc0[1] += a * ww.y;
                acc0[2] += a * ww.z; acc0[3] += a * ww.w;
            }
            float2 xv0 = __ldcg(&d_x2[brow]);
            float g0[4];
#pragma unroll
            for (int g = 0; g < 4; ++g) {
                g0[g] = acc0[g] + bb[g] + xv0.x * u0[g] + xv0.y * u1[g];
            }
            c0 = sigm(g0[1]) * c0 + sigm(g0[0]) * tanhf(g0[2]);
            float h0v = sigm(g0[3]) * tanhf(c0);
            float* hw = d_hbuf[td & 1];
            __stcg(&hw[brow * 256 + H], h0v);
        }
        gridbar();

        // ---- phase B: q projection (tid<512, bit-identical sum order) ----
        const float* hn = d_hbuf[td & 1];
        if (tid < 512)
            sh_h[tid >> 8][tid & 255] = __ldcg(&hn[(ab + (tid >> 8)) * 256 + (tid & 255)]);
        __syncthreads();
        if (tid < 512) {
            int qrow = tid >> 8, qcol = tid & 255;
            float q0 = 0.0f;
#pragma unroll 16
            for (int k = 0; k < 256; ++k) {
                float wq = d_WqT[k * 256 + qcol];
                q0 += sh_h[qrow][k] * wq;
            }
            sh_q[qrow][qcol] = q0;
        }
        __syncthreads();

        // ---- attention: compacted unmasked list + 1-deep prefetch (bit-identical math) ----
        int r = w & 1;          // row within pair
        int ws = w >> 1;        // 0..15
        int s_l = ws + 16 * lane;                    // this lane's s
        bool m_l = (sh_mask[r][s_l >> 5] >> (s_l & 31)) & 1u;
        if (m_l) sh_logit[r][s_l] = MASKV;
        unsigned um = __ballot_sync(0xffffffffu, !m_l);
        float bz = -1e30f; int bi = 0x7fffffff;
        const float4* q4 = (const float4*)&sh_q[r][0];
        const float4* v4 = (const float4*)&sh_v[0];
        float4 vq0 = v4[lane], vq1 = v4[32 + lane];
        float4 qq0 = q4[lane], qq1 = q4[32 + lane];
        const float* rpbase = &d_refproj[(ab + r) * 512 * 256];
        const float* gb = &d_gumb[((long long)td * 256 + (ab + r)) * 512];

        int pos = __ffs(um) - 1;
        float4 a0, a1;
        if (um) {
            const float4* rp4 = (const float4*)(rpbase + (ws + 16 * pos) * 256);
            a0 = __ldcg(rp4 + lane);
            a1 = __ldcg(rp4 + 32 + lane);
        }
        while (um) {
            int cur = ws + 16 * pos;
            um &= um - 1u;
            pos = __ffs(um) - 1;
            float4 n0, n1;
            if (um) {
                const float4* rp4 = (const float4*)(rpbase + (ws + 16 * pos) * 256);
                n0 = __ldcg(rp4 + lane);
                n1 = __ldcg(rp4 + 32 + lane);
            }
            float p;
            p  = vq0.x * tanh_r(qq0.x + a0.x);
            p  = fmaf(vq0.y, tanh_r(qq0.y + a0.y), p);
            p  = fmaf(vq0.z, tanh_r(qq0.z + a0.z), p);
            p  = fmaf(vq0.w, tanh_r(qq0.w + a0.w), p);
            p  = fmaf(vq1.x, tanh_r(qq1.x + a1.x), p);
            p  = fmaf(vq1.y, tanh_r(qq1.y + a1.y), p);
            p  = fmaf(vq1.z, tanh_r(qq1.z + a1.z), p);
            p  = fmaf(vq1.w, tanh_r(qq1.w + a1.w), p);
            p += __shfl_xor_sync(0xffffffffu, p, 16);
            p += __shfl_xor_sync(0xffffffffu, p, 8);
            p += __shfl_xor_sync(0xffffffffu, p, 4);
            p += __shfl_xor_sync(0xffffffffu, p, 2);
            p += __shfl_xor_sync(0xffffffffu, p, 1);
            if (lane == 0) {
                sh_logit[r][cur] = p;
                float z = p + gb[cur];
                if (z > bz) { bz = z; bi = cur; }
            }
            a0 = n0; a1 = n1;
        }
        if (lane == 0) { sh_bz[w] = bz; sh_bi[w] = bi; }
        __syncthreads();

        if (w < 2) {
            int rr = w;
            if (lane == 0) {
                float bv = -1e30f; int bidx = 0x7fffffff;
#pragma unroll
                for (int i = rr; i < 32; i += 2) {
                    if (sh_bz[i] > bv || (sh_bz[i] == bv && sh_bi[i] < bidx)) {
                        bv = sh_bz[i]; bidx = sh_bi[i];
                    }
                }
                sh_ch[rr] = bidx;
            }
            __syncwarp();
            int chosen = sh_ch[rr];
            float m = -1e30f;
            for (int s = lane; s < 512; s += 32) m = fmaxf(m, sh_logit[rr][s]);
            m = fmaxf(m, __shfl_xor_sync(0xffffffffu, m, 16));
            m = fmaxf(m, __shfl_xor_sync(0xffffffffu, m, 8));
            m = fmaxf(m, __shfl_xor_sync(0xffffffffu, m, 4));
            m = fmaxf(m, __shfl_xor_sync(0xffffffffu, m, 2));
            m = fmaxf(m, __shfl_xor_sync(0xffffffffu, m, 1));
            float es = 0.0f;
            for (int s = lane; s < 512; s += 32) es += expf(sh_logit[rr][s] - m);
            es += __shfl_xor_sync(0xffffffffu, es, 16);
            es += __shfl_xor_sync(0xffffffffu, es, 8);
            es += __shfl_xor_sync(0xffffffffu, es, 4);
            es += __shfl_xor_sync(0xffffffffu, es, 2);
            es += __shfl_xor_sync(0xffffffffu, es, 1);
            if (lane == 0) {
                int b = ab + rr;
                float lp = sh_logit[rr][chosen] - m - logf(es);
                out[b * (NSs - 1) + td] = lp;
                out[OUT_IDX_OFF + b * NSs + td + 1] = (float)chosen;
                sh_mask[rr][chosen >> 5] |= (1u << (chosen & 31));
                float2 nx;
                nx.x = inp[b * 1024 + chosen * 2];
                nx.y = inp[b * 1024 + chosen * 2 + 1];
                __stcg(&d_x2[b], nx);
            }
        }
        gridbar();
    }
}

// ---------------- host ----------------
extern "C" void kernel_launch(void* const* d_in, const int* in_sizes, int n_in,
                              void* d_out, int out_size) {
    const float* inputs  = (const float*)d_in[0];
    const float* W_embed = (const float*)d_in[1];
    const float* eWih    = (const float*)d_in[2];
    const float* eWhh    = (const float*)d_in[3];
    const float* ebih    = (const float*)d_in[4];
    const float* ebhh    = (const float*)d_in[5];
    const float* dWih    = (const float*)d_in[6];
    const float* dWhh    = (const float*)d_in[7];
    const float* dbih    = (const float*)d_in[8];
    const float* dbhh    = (const float*)d_in[9];
    const float* Wq      = (const float*)d_in[10];
    const float* Wref    = (const float*)d_in[11];
    const float* v       = (const float*)d_in[12];
    float* out = (float*)d_out;

    static int attr_done = 0;
    if (!attr_done) {
        cudaFuncSetAttribute(k_enc, cudaFuncAttributeMaxDynamicSharedMemorySize, DSMEM_BYTES);
        cudaFuncSetAttribute(k_dec, cudaFuncAttributeMaxDynamicSharedMemorySize, DSMEM_BYTES);
        attr_done = 1;
    }

    k_init<<<(NSs - 1) * NBb, 512>>>(inputs, W_embed, eWih, eWhh, ebih, ebhh,
                                     dWih, dWhh, dbih, dbhh, Wq, Wref, out);
    k_enc<<<NBLK, 512, DSMEM_BYTES>>>(inputs);
    k_refproj<<<dim3(4, 2048), 256>>>();
    k_dec<<<NBLK, 1024, DSMEM_BYTES>>>(inputs, v, out);
}